// round 12
// baseline (speedup 1.0000x reference)
#include <cuda_runtime.h>
#include <cuda_fp16.h>
#include <math.h>
#include <stdint.h>

#define B_ROWS 65536
#define S_DIM  376
#define A_DIM  17
#define H1_DIM 400
#define H2_DIM 300
#define K_FLOWS 15
#define HEAD_N 559

#define KP0 384
#define NB1 448
#define KI1 416
#define NB2 320
#define KP2 320
#define NB3 576

// ---------------- scratch (static device globals; no allocation) -------------
// NOTE: device globals are zero-initialized; padding columns that are never
// written stay 0, which downstream K-reads rely on.
__device__ __half g_x16[(size_t)B_ROWS * KP0];
__device__ __half g_h1[(size_t)B_ROWS * NB1];
__device__ __half g_h2[(size_t)B_ROWS * NB2];
// heads, interleaved-by-8: element (row, col) at [ (col/8)*B_ROWS*8 + row*8 + col%8 ]
__device__ __half g_h3[(size_t)B_ROWS * NB3];

__device__ __half g_W1[KP0 * NB1];
__device__ __half g_W2[NB1 * NB2];
__device__ __half g_Wh[KP2 * NB3];
__device__ float  g_bh[HEAD_N];

// ---------------- small helpers ----------------------------------------------
__device__ __forceinline__ uint32_t smem_u32(const void* p) {
    return (uint32_t)__cvta_generic_to_shared(p);
}
__device__ __forceinline__ void cp16(uint32_t dst, const void* src) {
    asm volatile("cp.async.cg.shared.global [%0], [%1], 16;\n" :: "r"(dst), "l"(src));
}
__device__ __forceinline__ void cp_commit() {
    asm volatile("cp.async.commit_group;\n" ::);
}
__device__ __forceinline__ void ldsm_x4(uint32_t* r, uint32_t addr) {
    asm volatile("ldmatrix.sync.aligned.m8n8.x4.shared.b16 {%0,%1,%2,%3}, [%4];\n"
                 : "=r"(r[0]), "=r"(r[1]), "=r"(r[2]), "=r"(r[3]) : "r"(addr));
}
__device__ __forceinline__ void ldsm_x4t(uint32_t* r, uint32_t addr) {
    asm volatile("ldmatrix.sync.aligned.m8n8.x4.trans.shared.b16 {%0,%1,%2,%3}, [%4];\n"
                 : "=r"(r[0]), "=r"(r[1]), "=r"(r[2]), "=r"(r[3]) : "r"(addr));
}
__device__ __forceinline__ void mma16816(float* c, const uint32_t* a, uint32_t b0, uint32_t b1) {
    asm volatile("mma.sync.aligned.m16n8k16.row.col.f32.f16.f16.f32 "
                 "{%0,%1,%2,%3}, {%4,%5,%6,%7}, {%8,%9}, {%0,%1,%2,%3};\n"
                 : "+f"(c[0]), "+f"(c[1]), "+f"(c[2]), "+f"(c[3])
                 : "r"(a[0]), "r"(a[1]), "r"(a[2]), "r"(a[3]), "r"(b0), "r"(b1));
}

__device__ __forceinline__ float fexp(float x)  { return __expf(x); }
__device__ __forceinline__ float flog(float x)  { return __logf(x); }
__device__ __forceinline__ float ftanh(float x) {
    float e = __expf(2.0f * x);
    return 1.0f - 2.0f / (e + 1.0f);
}

// A-tile smem addressing: 2 rows per 128B line; conflict-free for ldsm + stores
__device__ __forceinline__ uint32_t a_addr(uint32_t base, int row, int c4) {
    int slot = ((row & 1) * 4) + ((c4 ^ ((row >> 1) & 3)) & 3);
    return base + (row >> 1) * 128 + slot * 16;
}

// ---------------- conversion / packing kernels --------------------------------
__global__ void convert_x(const float* __restrict__ x, __half* __restrict__ o)
{
    size_t g = (size_t)blockIdx.x * blockDim.x + threadIdx.x;
    const size_t total = (size_t)B_ROWS * (KP0 / 8);
    if (g >= total) return;
    int m  = (int)(g / (KP0 / 8));
    int k0 = (int)(g - (size_t)m * (KP0 / 8)) * 8;
    __half h[8];
    if (k0 + 8 <= S_DIM) {
        const float4* src = reinterpret_cast<const float4*>(x + (size_t)m * S_DIM + k0);
        float4 a = src[0], b = src[1];
        h[0]=__float2half(a.x); h[1]=__float2half(a.y);
        h[2]=__float2half(a.z); h[3]=__float2half(a.w);
        h[4]=__float2half(b.x); h[5]=__float2half(b.y);
        h[6]=__float2half(b.z); h[7]=__float2half(b.w);
    } else {
#pragma unroll
        for (int i = 0; i < 8; i++) h[i] = __float2half(0.0f);
    }
    *reinterpret_cast<uint4*>(o + (size_t)m * KP0 + k0) = *reinterpret_cast<uint4*>(h);
}

#define W1_ELEMS (KP0 * NB1)
#define W2_ELEMS (NB1 * NB2)
#define WH_ELEMS (KP2 * NB3)
__global__ void prep_weights(
    const float* __restrict__ W1,  const float* __restrict__ W2,
    const float* __restrict__ Wmu, const float* __restrict__ bmu,
    const float* __restrict__ Wlv, const float* __restrict__ blv,
    const float* __restrict__ Wu,  const float* __restrict__ bu,
    const float* __restrict__ Ww,  const float* __restrict__ bw,
    const float* __restrict__ Wb,  const float* __restrict__ bb)
{
    int idx = blockIdx.x * blockDim.x + threadIdx.x;
    if (idx < W1_ELEMS) {
        int k = idx / NB1, n = idx - k * NB1;
        g_W1[idx] = __float2half((k < S_DIM && n < H1_DIM) ? W1[(size_t)k * H1_DIM + n] : 0.0f);
    }
    int i2 = idx - W1_ELEMS;
    if (i2 >= 0 && i2 < W2_ELEMS) {
        int k = i2 / NB2, n = i2 - k * NB2;
        g_W2[i2] = __float2half((k < H1_DIM && n < H2_DIM) ? W2[(size_t)k * H2_DIM + n] : 0.0f);
    }
    int i3 = idx - (W1_ELEMS + W2_ELEMS);
    if (i3 >= 0 && i3 < WH_ELEMS) {
        int k = i3 / NB3, c = i3 - k * NB3;
        float v = 0.0f;
        if (k < H2_DIM) {
            if      (c < 17)  v = Wmu[k * 17  + c];
            else if (c < 34)  v = Wlv[k * 17  + (c - 17)];
            else if (c < 289) v = Wu [k * 255 + (c - 34)];
            else if (c < 544) v = Ww [k * 255 + (c - 289)];
            else if (c < 559) v = Wb [k * 15  + (c - 544)];
        }
        g_Wh[i3] = __float2half(v);
    }
    if (idx < HEAD_N) {
        int c = idx;
        float v;
        if      (c < 17)  v = bmu[c];
        else if (c < 34)  v = blv[c - 17];
        else if (c < 289) v = bu [c - 34];
        else if (c < 544) v = bw [c - 289];
        else              v = bb [c - 544];
        g_bh[c] = v;
    }
}

// ---------------- tensor-core GEMM (mma.sync fp16) ----------------------------
// Block tile 256(M) x 64(N) x 32(K); 128 threads = 4 warps, warp tile 64x64.
// Ragged-N trim: per-CTA cnt8 = ceil((N-n0)/8) column-groups; B loads, ldsm,
// MMA and stores are skipped for groups >= cnt8 (branch-separated full path).
#define STAGES 5
#define A_BYTES 16384
#define STAGE_BYTES 20480

template <int OUT>
__global__ __launch_bounds__(128, 2) void gemm_mma(
    const __half* __restrict__ A, int lda, int Kiter,
    const __half* __restrict__ B, int ldb,
    const float* __restrict__ bias, int N,
    __half* __restrict__ Ch, int ldc)
{
    extern __shared__ char smem[];
    const uint32_t sb = smem_u32(smem);

    const int tid  = threadIdx.x;
    const int lane = tid & 31;
    const int wid  = tid >> 5;
    const int m0   = blockIdx.y * 256;
    const int n0   = blockIdx.x * 64;
    const int KT   = Kiter / 32;
    const int cnt8 = min(8, (N - n0 + 7) >> 3);   // real 8-col groups this CTA
    const bool full = (cnt8 == 8);

    float acc[4][8][4];
#pragma unroll
    for (int i = 0; i < 4; i++)
#pragma unroll
        for (int j = 0; j < 8; j++)
#pragma unroll
            for (int q = 0; q < 4; q++) acc[i][j][q] = 0.0f;

    auto load_stage = [&](int s, int kt) {
        const uint32_t stA = sb + s * STAGE_BYTES;
        const uint32_t stB = stA + A_BYTES;
#pragma unroll
        for (int q = 0; q < 8; q++) {
            int g   = tid + 128 * q;
            int row = g >> 2;
            int c4  = g & 3;
            const __half* src = A + (size_t)(m0 + row) * lda + kt * 32 + c4 * 8;
            cp16(a_addr(stA, row, c4), src);
        }
#pragma unroll
        for (int q = 0; q < 2; q++) {
            int g   = tid + 128 * q;
            int row = g >> 3;
            int c8  = g & 7;
            if (c8 < cnt8) {
                const __half* src = B + (size_t)(kt * 32 + row) * ldb + n0 + c8 * 8;
                cp16(stB + row * 128 + ((c8 ^ (row & 7)) * 16), src);
            }
        }
        cp_commit();
    };

    load_stage(0, 0);
    load_stage(1, 1);
    load_stage(2, 2);
    load_stage(3, 3);

    int sc = 0, sp = 4;
    for (int c = 0; c < KT; c++) {
        asm volatile("cp.async.wait_group 3;" ::: "memory");
        __syncthreads();

        if (c + 4 < KT) load_stage(sp, c + 4);
        else            cp_commit();
        if (++sp == STAGES) sp = 0;

        const uint32_t stA = sb + sc * STAGE_BYTES;
        const uint32_t stB = stA + A_BYTES;
        if (++sc == STAGES) sc = 0;

#pragma unroll
        for (int kk = 0; kk < 2; kk++) {
            uint32_t ah[4][4], bh[4][4];
            {
                int rbase = lane & 15;
                int q     = kk * 2 + (lane >> 4);
#pragma unroll
                for (int mi = 0; mi < 4; mi++) {
                    int r = wid * 64 + mi * 16 + rbase;
                    ldsm_x4(ah[mi], a_addr(stA, r, q));
                }
            }
            const int row  = kk * 16 + (lane & 15);
            const int half = (lane >> 4);
            if (full) {
#pragma unroll
                for (int nb = 0; nb < 4; nb++) {
                    int c8 = nb * 2 + half;
                    ldsm_x4t(bh[nb], stB + row * 128 + ((c8 ^ (row & 7)) * 16));
                }
#pragma unroll
                for (int mi = 0; mi < 4; mi++) {
#pragma unroll
                    for (int n8 = 0; n8 < 8; n8++) {
                        int nb = n8 >> 1, j = (n8 & 1) * 2;
                        mma16816(acc[mi][n8], ah[mi], bh[nb][j], bh[nb][j + 1]);
                    }
                }
            } else {
                const int nbcnt = (cnt8 + 1) >> 1;
#pragma unroll
                for (int nb = 0; nb < 4; nb++) {
                    if (nb < nbcnt) {
                        int c8 = nb * 2 + half;
                        // clamp to loaded region (half may exceed cnt8 by 1; B row
                        // data for that group is stale but result is discarded)
                        int c8c = (c8 < cnt8) ? c8 : (cnt8 - 1);
                        ldsm_x4t(bh[nb], stB + row * 128 + ((c8c ^ (row & 7)) * 16));
                    }
                }
#pragma unroll
                for (int mi = 0; mi < 4; mi++) {
#pragma unroll
                    for (int n8 = 0; n8 < 8; n8++) {
                        if (n8 < cnt8) {
                            int nb = n8 >> 1, j = (n8 & 1) * 2;
                            mma16816(acc[mi][n8], ah[mi], bh[nb][j], bh[nb][j + 1]);
                        }
                    }
                }
            }
        }
    }

    // ---- epilogue ----
    const int lr = lane >> 2;
    const int lc = (lane & 3) * 2;
#pragma unroll
    for (int mi = 0; mi < 4; mi++) {
#pragma unroll
        for (int n8 = 0; n8 < 8; n8++) {
            if (n8 >= cnt8) continue;
            int col = n0 + n8 * 8 + lc;
            float b0 = (col     < N) ? bias[col]     : 0.0f;
            float b1 = (col + 1 < N) ? bias[col + 1] : 0.0f;
#pragma unroll
            for (int h = 0; h < 2; h++) {
                int row = m0 + wid * 64 + mi * 16 + h * 8 + lr;
                float v0 = acc[mi][n8][2 * h + 0] + b0;
                float v1 = acc[mi][n8][2 * h + 1] + b1;
                __half2 hv;
                if (OUT == 1) {
                    v0 = (col     < N) ? fmaxf(v0, 0.0f) : 0.0f;
                    v1 = (col + 1 < N) ? fmaxf(v1, 0.0f) : 0.0f;
                    hv.x = __float2half(v0); hv.y = __float2half(v1);
                    *reinterpret_cast<__half2*>(&Ch[(size_t)row * ldc + col]) = hv;
                } else {
                    // mask padding so interleaved store stays clean
                    v0 = (col     < N) ? v0 : 0.0f;
                    v1 = (col + 1 < N) ? v1 : 0.0f;
                    hv.x = __float2half(v0); hv.y = __float2half(v1);
                    size_t idx = ((size_t)(col >> 3) * B_ROWS + row) * 8 + (col & 7);
                    *reinterpret_cast<__half2*>(&Ch[idx]) = hv;
                }
            }
        }
    }
}

// ---------------- flow: one THREAD per batch row -------------------------------
__device__ __forceinline__ float h3grp(const uint4* G, int off) {
    const __half* h = reinterpret_cast<const __half*>(G);
    return __half2float(h[off]);
}

__global__ __launch_bounds__(256) void flow_kernel(
    const float* __restrict__ eps, float* __restrict__ out)
{
    __shared__ float sbuf[256 * A_DIM];
    const int tid = threadIdx.x;
    const size_t row = (size_t)blockIdx.x * 256 + tid;

    {
        const float* src = eps + (size_t)blockIdx.x * 256 * A_DIM;
#pragma unroll 4
        for (int i = tid; i < 256 * A_DIM; i += 256) sbuf[i] = src[i];
    }
    __syncthreads();

    float e[A_DIM];
#pragma unroll
    for (int a = 0; a < A_DIM; a++) e[a] = sbuf[tid * A_DIM + a];

    auto ldg8 = [&](int g) -> uint4 {
        return *reinterpret_cast<const uint4*>(g_h3 + ((size_t)g * B_ROWS + row) * 8);
    };

    float z[A_DIM];
    float lp = 0.0f;
    {
        uint4 G[5];
#pragma unroll
        for (int g = 0; g < 5; g++) G[g] = ldg8(g);
#pragma unroll
        for (int a = 0; a < A_DIM; a++) {
            float mu = ftanh(h3grp(G, a));
            float lv = ftanh(h3grp(G, 17 + a));
            z[a] = mu + fexp(lv) * e[a];
            lp += -0.5f * e[a] * e[a] - lv;
        }
    }

    float ldj = 0.0f;
#pragma unroll
    for (int k = 0; k < K_FLOWS; k++) {
        const int bu = 34 + 17 * k;
        const int bw = 289 + 17 * k;
        const int gu0 = bu >> 3, ou = bu & 7;
        const int gw0 = bw >> 3, ow = bw & 7;
        uint4 GU[3], GW[3];
#pragma unroll
        for (int g = 0; g < 3; g++) { GU[g] = ldg8(gu0 + g); GW[g] = ldg8(gw0 + g); }

        float uw = 0.0f, wns = 0.0f, wz = 0.0f;
#pragma unroll
        for (int a = 0; a < A_DIM; a++) {
            float u = h3grp(GU, ou + a);
            float w = h3grp(GW, ow + a);
            uw  = fmaf(w, u, uw);
            wns = fmaf(w, w, wns);
            wz  = fmaf(w, z[a], wz);
        }
        const int cb = 544 + k;
        float bk = __half2float(g_h3[((size_t)(cb >> 3) * B_ROWS + row) * 8 + (cb & 7)]);

        float sp    = fmaxf(uw, 0.0f) + flog(1.0f + fexp(-fabsf(uw)));
        float m_uw  = -1.0f + sp;
        float scale = (m_uw - uw) / wns;
        float t     = ftanh(wz + bk);
#pragma unroll
        for (int a = 0; a < A_DIM; a++) {
            float u = h3grp(GU, ou + a);
            float w = h3grp(GW, ow + a);
            z[a] = fmaf(fmaf(scale, w, u), t, z[a]);
        }
        float psi_u = m_uw * (1.0f - t * t);
        ldj += flog(fabsf(1.0f + psi_u));
    }

    __syncthreads();
#pragma unroll
    for (int a = 0; a < A_DIM; a++) sbuf[tid * A_DIM + a] = z[a];
    __syncthreads();
    {
        float* dst = out + (size_t)blockIdx.x * 256 * A_DIM;
#pragma unroll 4
        for (int i = tid; i < 256 * A_DIM; i += 256) dst[i] = sbuf[i];
    }

    lp -= 0.5f * (float)A_DIM * 1.8378770664093453f;
    float lpf = lp - ldj;
    out[(size_t)B_ROWS * A_DIM + row]          = fexp(lpf);
    out[(size_t)B_ROWS * A_DIM + B_ROWS + row] = lpf;
}

// ---------------- launch ------------------------------------------------------
extern "C" void kernel_launch(void* const* d_in, const int* in_sizes, int n_in,
                              void* d_out, int out_size)
{
    (void)in_sizes; (void)n_in; (void)out_size;

    const float* x   = (const float*)d_in[0];
    const float* eps = (const float*)d_in[1];
    const float* W1  = (const float*)d_in[2];
    const float* b1  = (const float*)d_in[3];
    const float* W2  = (const float*)d_in[4];
    const float* b2  = (const float*)d_in[5];
    const float* Wmu = (const float*)d_in[6];
    const float* bmu = (const float*)d_in[7];
    const float* Wlv = (const float*)d_in[8];
    const float* blv = (const float*)d_in[9];
    const float* Wu  = (const float*)d_in[10];
    const float* bu  = (const float*)d_in[11];
    const float* Ww  = (const float*)d_in[12];
    const float* bw  = (const float*)d_in[13];
    const float* Wb  = (const float*)d_in[14];
    const float* bb  = (const float*)d_in[15];
    float* out = (float*)d_out;

    __half *x16, *h1, *h2, *h3, *w1, *w2, *wh;
    float *bhp;
    cudaGetSymbolAddress((void**)&x16, g_x16);
    cudaGetSymbolAddress((void**)&h1,  g_h1);
    cudaGetSymbolAddress((void**)&h2,  g_h2);
    cudaGetSymbolAddress((void**)&h3,  g_h3);
    cudaGetSymbolAddress((void**)&w1,  g_W1);
    cudaGetSymbolAddress((void**)&w2,  g_W2);
    cudaGetSymbolAddress((void**)&wh,  g_Wh);
    cudaGetSymbolAddress((void**)&bhp, g_bh);

    convert_x<<<(int)(((size_t)B_ROWS * (KP0 / 8) + 255) / 256), 256>>>(x, x16);
    const int prep_total = W1_ELEMS + W2_ELEMS + WH_ELEMS;
    prep_weights<<<(prep_total + 255) / 256, 256>>>(W1, W2, Wmu, bmu, Wlv, blv,
                                                    Wu, bu, Ww, bw, Wb, bb);

    const int smem_bytes = STAGES * STAGE_BYTES;   // 102400
    cudaFuncSetAttribute(gemm_mma<1>, cudaFuncAttributeMaxDynamicSharedMemorySize, smem_bytes);
    cudaFuncSetAttribute(gemm_mma<0>, cudaFuncAttributeMaxDynamicSharedMemorySize, smem_bytes);

    dim3 blk(128);
    gemm_mma<1><<<dim3(NB1 / 64, B_ROWS / 256), blk, smem_bytes>>>(
        x16, KP0, KP0, w1, NB1, b1, H1_DIM, h1, NB1);
    gemm_mma<1><<<dim3(NB2 / 64, B_ROWS / 256), blk, smem_bytes>>>(
        h1, NB1, KI1, w2, NB2, b2, H2_DIM, h2, NB2);
    gemm_mma<0><<<dim3(NB3 / 64, B_ROWS / 256), blk, smem_bytes>>>(
        h2, KP2, KP2, wh, NB3, bhp, HEAD_N, h3, NB3);

    flow_kernel<<<B_ROWS / 256, 256>>>(eps, out);
}

// round 13
// speedup vs baseline: 1.1903x; 1.1903x over previous
#include <cuda_runtime.h>
#include <cuda_fp16.h>
#include <math.h>
#include <stdint.h>

#define B_ROWS 65536
#define S_DIM  376
#define A_DIM  17
#define H1_DIM 400
#define H2_DIM 300
#define K_FLOWS 15
#define HEAD_N 559

#define KP0 384
#define NB1 448
#define KI1 416
#define NB2 320
#define KP2 320
#define NB3 576

// ---------------- scratch (static device globals; no allocation) -------------
// device globals are zero-initialized; padding columns never written stay 0
__device__ __half g_x16[(size_t)B_ROWS * KP0];
__device__ __half g_h1[(size_t)B_ROWS * NB1];
__device__ __half g_h2[(size_t)B_ROWS * NB2];
// heads, interleaved-by-8: element (row, col) at [ (col/8)*B_ROWS*8 + row*8 + col%8 ]
__device__ __half g_h3[(size_t)B_ROWS * NB3];

__device__ __half g_W1[KP0 * NB1];
__device__ __half g_W2[NB1 * NB2];
__device__ __half g_Wh[KP2 * NB3];
__device__ float  g_bh[HEAD_N];

// ---------------- small helpers ----------------------------------------------
__device__ __forceinline__ uint32_t smem_u32(const void* p) {
    return (uint32_t)__cvta_generic_to_shared(p);
}
__device__ __forceinline__ void cp16(uint32_t dst, const void* src) {
    asm volatile("cp.async.cg.shared.global [%0], [%1], 16;\n" :: "r"(dst), "l"(src));
}
__device__ __forceinline__ void cp_commit() {
    asm volatile("cp.async.commit_group;\n" ::);
}
__device__ __forceinline__ void ldsm_x4(uint32_t* r, uint32_t addr) {
    asm volatile("ldmatrix.sync.aligned.m8n8.x4.shared.b16 {%0,%1,%2,%3}, [%4];\n"
                 : "=r"(r[0]), "=r"(r[1]), "=r"(r[2]), "=r"(r[3]) : "r"(addr));
}
__device__ __forceinline__ void ldsm_x4t(uint32_t* r, uint32_t addr) {
    asm volatile("ldmatrix.sync.aligned.m8n8.x4.trans.shared.b16 {%0,%1,%2,%3}, [%4];\n"
                 : "=r"(r[0]), "=r"(r[1]), "=r"(r[2]), "=r"(r[3]) : "r"(addr));
}
__device__ __forceinline__ void mma16816(float* c, const uint32_t* a, uint32_t b0, uint32_t b1) {
    asm volatile("mma.sync.aligned.m16n8k16.row.col.f32.f16.f16.f32 "
                 "{%0,%1,%2,%3}, {%4,%5,%6,%7}, {%8,%9}, {%0,%1,%2,%3};\n"
                 : "+f"(c[0]), "+f"(c[1]), "+f"(c[2]), "+f"(c[3])
                 : "r"(a[0]), "r"(a[1]), "r"(a[2]), "r"(a[3]), "r"(b0), "r"(b1));
}

__device__ __forceinline__ float fexp(float x)  { return __expf(x); }
__device__ __forceinline__ float flog(float x)  { return __logf(x); }
__device__ __forceinline__ float ftanh(float x) {
    float e = __expf(2.0f * x);
    return 1.0f - 2.0f / (e + 1.0f);
}

// A-tile smem addressing: 2 rows per 128B line; conflict-free for ldsm + stores
__device__ __forceinline__ uint32_t a_addr(uint32_t base, int row, int c4) {
    int slot = ((row & 1) * 4) + ((c4 ^ ((row >> 1) & 3)) & 3);
    return base + (row >> 1) * 128 + slot * 16;
}

// ---------------- conversion / packing kernels --------------------------------
__global__ void convert_x(const float* __restrict__ x, __half* __restrict__ o)
{
    size_t g = (size_t)blockIdx.x * blockDim.x + threadIdx.x;
    const size_t total = (size_t)B_ROWS * (KP0 / 8);
    if (g >= total) return;
    int m  = (int)(g / (KP0 / 8));
    int k0 = (int)(g - (size_t)m * (KP0 / 8)) * 8;
    __half h[8];
    if (k0 + 8 <= S_DIM) {
        const float4* src = reinterpret_cast<const float4*>(x + (size_t)m * S_DIM + k0);
        float4 a = src[0], b = src[1];
        h[0]=__float2half(a.x); h[1]=__float2half(a.y);
        h[2]=__float2half(a.z); h[3]=__float2half(a.w);
        h[4]=__float2half(b.x); h[5]=__float2half(b.y);
        h[6]=__float2half(b.z); h[7]=__float2half(b.w);
    } else {
#pragma unroll
        for (int i = 0; i < 8; i++) h[i] = __float2half(0.0f);
    }
    *reinterpret_cast<uint4*>(o + (size_t)m * KP0 + k0) = *reinterpret_cast<uint4*>(h);
}

#define W1_ELEMS (KP0 * NB1)
#define W2_ELEMS (NB1 * NB2)
#define WH_ELEMS (KP2 * NB3)
__global__ void prep_weights(
    const float* __restrict__ W1,  const float* __restrict__ W2,
    const float* __restrict__ Wmu, const float* __restrict__ bmu,
    const float* __restrict__ Wlv, const float* __restrict__ blv,
    const float* __restrict__ Wu,  const float* __restrict__ bu,
    const float* __restrict__ Ww,  const float* __restrict__ bw,
    const float* __restrict__ Wb,  const float* __restrict__ bb)
{
    int idx = blockIdx.x * blockDim.x + threadIdx.x;
    if (idx < W1_ELEMS) {
        int k = idx / NB1, n = idx - k * NB1;
        g_W1[idx] = __float2half((k < S_DIM && n < H1_DIM) ? W1[(size_t)k * H1_DIM + n] : 0.0f);
    }
    int i2 = idx - W1_ELEMS;
    if (i2 >= 0 && i2 < W2_ELEMS) {
        int k = i2 / NB2, n = i2 - k * NB2;
        g_W2[i2] = __float2half((k < H1_DIM && n < H2_DIM) ? W2[(size_t)k * H2_DIM + n] : 0.0f);
    }
    int i3 = idx - (W1_ELEMS + W2_ELEMS);
    if (i3 >= 0 && i3 < WH_ELEMS) {
        int k = i3 / NB3, c = i3 - k * NB3;
        float v = 0.0f;
        if (k < H2_DIM) {
            if      (c < 17)  v = Wmu[k * 17  + c];
            else if (c < 34)  v = Wlv[k * 17  + (c - 17)];
            else if (c < 289) v = Wu [k * 255 + (c - 34)];
            else if (c < 544) v = Ww [k * 255 + (c - 289)];
            else if (c < 559) v = Wb [k * 15  + (c - 544)];
        }
        g_Wh[i3] = __float2half(v);
    }
    if (idx < HEAD_N) {
        int c = idx;
        float v;
        if      (c < 17)  v = bmu[c];
        else if (c < 34)  v = blv[c - 17];
        else if (c < 289) v = bu [c - 34];
        else if (c < 544) v = bw [c - 289];
        else              v = bb [c - 544];
        g_bh[c] = v;
    }
}

// ---------------- tensor-core GEMM (mma.sync fp16) ----------------------------
// Block tile 256(M) x (NG*8)(N) x 32(K); 128 threads = 4 warps, warp tile 64xN.
// NG is a COMPILE-TIME group count (8 = full 64-col tile); NG=8 path is
// identical to the proven full kernel. Partial tiles run as separate launches.
#define STAGES 5
#define A_BYTES 16384
#define STAGE_BYTES 20480

template <int OUT, int NG>
__global__ __launch_bounds__(128, 2) void gemm_mma(
    const __half* __restrict__ A, int lda, int Kiter,
    const __half* __restrict__ B, int ldb,
    const float* __restrict__ bias, int N,
    __half* __restrict__ Ch, int ldc, int n_base)
{
    extern __shared__ char smem[];
    const uint32_t sb = smem_u32(smem);

    const int tid  = threadIdx.x;
    const int lane = tid & 31;
    const int wid  = tid >> 5;
    const int m0   = blockIdx.y * 256;
    const int n0   = n_base + blockIdx.x * 64;
    const int KT   = Kiter / 32;

    float acc[4][NG][4];
#pragma unroll
    for (int i = 0; i < 4; i++)
#pragma unroll
        for (int j = 0; j < NG; j++)
#pragma unroll
            for (int q = 0; q < 4; q++) acc[i][j][q] = 0.0f;

    auto load_stage = [&](int s, int kt) {
        const uint32_t stA = sb + s * STAGE_BYTES;
        const uint32_t stB = stA + A_BYTES;
#pragma unroll
        for (int q = 0; q < 8; q++) {
            int g   = tid + 128 * q;
            int row = g >> 2;
            int c4  = g & 3;
            const __half* src = A + (size_t)(m0 + row) * lda + kt * 32 + c4 * 8;
            cp16(a_addr(stA, row, c4), src);
        }
#pragma unroll
        for (int q = 0; q < 2; q++) {
            int g   = tid + 128 * q;
            int row = g >> 3;
            int c8  = g & 7;
            if (c8 < NG) {   // compile-time for NG==8
                const __half* src = B + (size_t)(kt * 32 + row) * ldb + n0 + c8 * 8;
                cp16(stB + row * 128 + ((c8 ^ (row & 7)) * 16), src);
            }
        }
        cp_commit();
    };

    load_stage(0, 0);
    load_stage(1, 1);
    load_stage(2, 2);
    load_stage(3, 3);

    int sc = 0, sp = 4;
    for (int c = 0; c < KT; c++) {
        asm volatile("cp.async.wait_group 3;" ::: "memory");
        __syncthreads();

        if (c + 4 < KT) load_stage(sp, c + 4);
        else            cp_commit();
        if (++sp == STAGES) sp = 0;

        const uint32_t stA = sb + sc * STAGE_BYTES;
        const uint32_t stB = stA + A_BYTES;
        if (++sc == STAGES) sc = 0;

#pragma unroll
        for (int kk = 0; kk < 2; kk++) {
            uint32_t ah[4][4], bh[(NG + 1) / 2][4];
            {
                int rbase = lane & 15;
                int q     = kk * 2 + (lane >> 4);
#pragma unroll
                for (int mi = 0; mi < 4; mi++) {
                    int r = wid * 64 + mi * 16 + rbase;
                    ldsm_x4(ah[mi], a_addr(stA, r, q));
                }
            }
            {
                int row  = kk * 16 + (lane & 15);
                int half = (lane >> 4);
#pragma unroll
                for (int nb = 0; nb < (NG + 1) / 2; nb++) {
                    int c8 = nb * 2 + half;   // NG even: c8 < NG always
                    ldsm_x4t(bh[nb], stB + row * 128 + ((c8 ^ (row & 7)) * 16));
                }
            }
#pragma unroll
            for (int mi = 0; mi < 4; mi++) {
#pragma unroll
                for (int n8 = 0; n8 < NG; n8++) {
                    int nb = n8 >> 1, j = (n8 & 1) * 2;
                    mma16816(acc[mi][n8], ah[mi], bh[nb][j], bh[nb][j + 1]);
                }
            }
        }
    }

    // ---- epilogue ----
    const int lr = lane >> 2;
    const int lc = (lane & 3) * 2;
#pragma unroll
    for (int mi = 0; mi < 4; mi++) {
#pragma unroll
        for (int n8 = 0; n8 < NG; n8++) {
            int col = n0 + n8 * 8 + lc;
            float b0 = (col     < N) ? bias[col]     : 0.0f;
            float b1 = (col + 1 < N) ? bias[col + 1] : 0.0f;
#pragma unroll
            for (int h = 0; h < 2; h++) {
                int row = m0 + wid * 64 + mi * 16 + h * 8 + lr;
                float v0 = acc[mi][n8][2 * h + 0] + b0;
                float v1 = acc[mi][n8][2 * h + 1] + b1;
                __half2 hv;
                if (OUT == 1) {
                    v0 = (col     < N) ? fmaxf(v0, 0.0f) : 0.0f;
                    v1 = (col + 1 < N) ? fmaxf(v1, 0.0f) : 0.0f;
                    hv.x = __float2half(v0); hv.y = __float2half(v1);
                    *reinterpret_cast<__half2*>(&Ch[(size_t)row * ldc + col]) = hv;
                } else {
                    hv.x = __float2half(v0); hv.y = __float2half(v1);
                    size_t idx = ((size_t)(col >> 3) * B_ROWS + row) * 8 + (col & 7);
                    *reinterpret_cast<__half2*>(&Ch[idx]) = hv;
                }
            }
        }
    }
}

// ---------------- flow: one THREAD per batch row -------------------------------
__device__ __forceinline__ float h3grp(const uint4* G, int off) {
    const __half* h = reinterpret_cast<const __half*>(G);
    return __half2float(h[off]);
}

__global__ __launch_bounds__(256) void flow_kernel(
    const float* __restrict__ eps, float* __restrict__ out)
{
    __shared__ float sbuf[256 * A_DIM];
    const int tid = threadIdx.x;
    const size_t row = (size_t)blockIdx.x * 256 + tid;

    {
        const float* src = eps + (size_t)blockIdx.x * 256 * A_DIM;
#pragma unroll 4
        for (int i = tid; i < 256 * A_DIM; i += 256) sbuf[i] = src[i];
    }
    __syncthreads();

    float e[A_DIM];
#pragma unroll
    for (int a = 0; a < A_DIM; a++) e[a] = sbuf[tid * A_DIM + a];

    auto ldg8 = [&](int g) -> uint4 {
        return *reinterpret_cast<const uint4*>(g_h3 + ((size_t)g * B_ROWS + row) * 8);
    };

    float z[A_DIM];
    float lp = 0.0f;
    {
        uint4 G[5];
#pragma unroll
        for (int g = 0; g < 5; g++) G[g] = ldg8(g);
#pragma unroll
        for (int a = 0; a < A_DIM; a++) {
            float mu = ftanh(h3grp(G, a));
            float lv = ftanh(h3grp(G, 17 + a));
            z[a] = mu + fexp(lv) * e[a];
            lp += -0.5f * e[a] * e[a] - lv;
        }
    }

    float ldj = 0.0f;
#pragma unroll
    for (int k = 0; k < K_FLOWS; k++) {
        const int bu = 34 + 17 * k;
        const int bw = 289 + 17 * k;
        const int gu0 = bu >> 3, ou = bu & 7;
        const int gw0 = bw >> 3, ow = bw & 7;
        uint4 GU[3], GW[3];
#pragma unroll
        for (int g = 0; g < 3; g++) { GU[g] = ldg8(gu0 + g); GW[g] = ldg8(gw0 + g); }

        float uw = 0.0f, wns = 0.0f, wz = 0.0f;
#pragma unroll
        for (int a = 0; a < A_DIM; a++) {
            float u = h3grp(GU, ou + a);
            float w = h3grp(GW, ow + a);
            uw  = fmaf(w, u, uw);
            wns = fmaf(w, w, wns);
            wz  = fmaf(w, z[a], wz);
        }
        const int cb = 544 + k;
        float bk = __half2float(g_h3[((size_t)(cb >> 3) * B_ROWS + row) * 8 + (cb & 7)]);

        float sp    = fmaxf(uw, 0.0f) + flog(1.0f + fexp(-fabsf(uw)));
        float m_uw  = -1.0f + sp;
        float scale = (m_uw - uw) / wns;
        float t     = ftanh(wz + bk);
#pragma unroll
        for (int a = 0; a < A_DIM; a++) {
            float u = h3grp(GU, ou + a);
            float w = h3grp(GW, ow + a);
            z[a] = fmaf(fmaf(scale, w, u), t, z[a]);
        }
        float psi_u = m_uw * (1.0f - t * t);
        ldj += flog(fabsf(1.0f + psi_u));
    }

    __syncthreads();
#pragma unroll
    for (int a = 0; a < A_DIM; a++) sbuf[tid * A_DIM + a] = z[a];
    __syncthreads();
    {
        float* dst = out + (size_t)blockIdx.x * 256 * A_DIM;
#pragma unroll 4
        for (int i = tid; i < 256 * A_DIM; i += 256) dst[i] = sbuf[i];
    }

    lp -= 0.5f * (float)A_DIM * 1.8378770664093453f;
    float lpf = lp - ldj;
    out[(size_t)B_ROWS * A_DIM + row]          = fexp(lpf);
    out[(size_t)B_ROWS * A_DIM + B_ROWS + row] = lpf;
}

// ---------------- launch ------------------------------------------------------
extern "C" void kernel_launch(void* const* d_in, const int* in_sizes, int n_in,
                              void* d_out, int out_size)
{
    (void)in_sizes; (void)n_in; (void)out_size;

    const float* x   = (const float*)d_in[0];
    const float* eps = (const float*)d_in[1];
    const float* W1  = (const float*)d_in[2];
    const float* b1  = (const float*)d_in[3];
    const float* W2  = (const float*)d_in[4];
    const float* b2  = (const float*)d_in[5];
    const float* Wmu = (const float*)d_in[6];
    const float* bmu = (const float*)d_in[7];
    const float* Wlv = (const float*)d_in[8];
    const float* blv = (const float*)d_in[9];
    const float* Wu  = (const float*)d_in[10];
    const float* bu  = (const float*)d_in[11];
    const float* Ww  = (const float*)d_in[12];
    const float* bw  = (const float*)d_in[13];
    const float* Wb  = (const float*)d_in[14];
    const float* bb  = (const float*)d_in[15];
    float* out = (float*)d_out;

    __half *x16, *h1, *h2, *h3, *w1, *w2, *wh;
    float *bhp;
    cudaGetSymbolAddress((void**)&x16, g_x16);
    cudaGetSymbolAddress((void**)&h1,  g_h1);
    cudaGetSymbolAddress((void**)&h2,  g_h2);
    cudaGetSymbolAddress((void**)&h3,  g_h3);
    cudaGetSymbolAddress((void**)&w1,  g_W1);
    cudaGetSymbolAddress((void**)&w2,  g_W2);
    cudaGetSymbolAddress((void**)&wh,  g_Wh);
    cudaGetSymbolAddress((void**)&bhp, g_bh);

    convert_x<<<(int)(((size_t)B_ROWS * (KP0 / 8) + 255) / 256), 256>>>(x, x16);
    const int prep_total = W1_ELEMS + W2_ELEMS + WH_ELEMS;
    prep_weights<<<(prep_total + 255) / 256, 256>>>(W1, W2, Wmu, bmu, Wlv, blv,
                                                    Wu, bu, Ww, bw, Wb, bb);

    const int smem_bytes = STAGES * STAGE_BYTES;   // 102400
    cudaFuncSetAttribute(gemm_mma<1, 8>, cudaFuncAttributeMaxDynamicSharedMemorySize, smem_bytes);
    cudaFuncSetAttribute(gemm_mma<1, 2>, cudaFuncAttributeMaxDynamicSharedMemorySize, smem_bytes);
    cudaFuncSetAttribute(gemm_mma<1, 6>, cudaFuncAttributeMaxDynamicSharedMemorySize, smem_bytes);
    cudaFuncSetAttribute(gemm_mma<0, 8>, cudaFuncAttributeMaxDynamicSharedMemorySize, smem_bytes);
    cudaFuncSetAttribute(gemm_mma<0, 6>, cudaFuncAttributeMaxDynamicSharedMemorySize, smem_bytes);

    dim3 blk(128);
    // layer 1: N=400 -> 6 full 64-col tiles + 16 cols (NG=2)
    gemm_mma<1, 8><<<dim3(6, B_ROWS / 256), blk, smem_bytes>>>(
        x16, KP0, KP0, w1, NB1, b1, H1_DIM, h1, NB1, 0);
    gemm_mma<1, 2><<<dim3(1, B_ROWS / 256), blk, smem_bytes>>>(
        x16, KP0, KP0, w1, NB1, b1, H1_DIM, h1, NB1, 384);
    // layer 2: N=300 -> 4 full tiles + 44 cols (NG=6)
    gemm_mma<1, 8><<<dim3(4, B_ROWS / 256), blk, smem_bytes>>>(
        h1, NB1, KI1, w2, NB2, b2, H2_DIM, h2, NB2, 0);
    gemm_mma<1, 6><<<dim3(1, B_ROWS / 256), blk, smem_bytes>>>(
        h1, NB1, KI1, w2, NB2, b2, H2_DIM, h2, NB2, 256);
    // heads: N=559 -> 8 full tiles + 47 cols (NG=6)
    gemm_mma<0, 8><<<dim3(8, B_ROWS / 256), blk, smem_bytes>>>(
        h2, KP2, KP2, wh, NB3, bhp, HEAD_N, h3, NB3, 0);
    gemm_mma<0, 6><<<dim3(1, B_ROWS / 256), blk, smem_bytes>>>(
        h2, KP2, KP2, wh, NB3, bhp, HEAD_N, h3, NB3, 512);

    flow_kernel<<<B_ROWS / 256, 256>>>(eps, out);
}

// round 14
// speedup vs baseline: 1.2349x; 1.0375x over previous
#include <cuda_runtime.h>
#include <cuda_fp16.h>
#include <math.h>
#include <stdint.h>

#define B_ROWS 65536
#define S_DIM  376
#define A_DIM  17
#define H1_DIM 400
#define H2_DIM 300
#define K_FLOWS 15
#define HEAD_N 559

#define KP0 384
#define NB1 448
#define KI1 416
#define NB2 320
#define KP2 320
#define NB3 576

// ---------------- scratch (static device globals; no allocation) -------------
// device globals are zero-initialized; padding columns never written stay 0
__device__ __half g_x16[(size_t)B_ROWS * KP0];
__device__ __half g_h1[(size_t)B_ROWS * NB1];
__device__ __half g_h2[(size_t)B_ROWS * NB2];
// heads, interleaved-by-8: element (row, col) at [ (col/8)*B_ROWS*8 + row*8 + col%8 ]
__device__ __half g_h3[(size_t)B_ROWS * NB3];

__device__ __half g_W1[KP0 * NB1];
__device__ __half g_W2[NB1 * NB2];
__device__ __half g_Wh[KP2 * NB3];
__device__ float  g_bh[HEAD_N];

// ---------------- small helpers ----------------------------------------------
__device__ __forceinline__ uint32_t smem_u32(const void* p) {
    return (uint32_t)__cvta_generic_to_shared(p);
}
__device__ __forceinline__ void cp16(uint32_t dst, const void* src) {
    asm volatile("cp.async.cg.shared.global [%0], [%1], 16;\n" :: "r"(dst), "l"(src));
}
__device__ __forceinline__ void cp_commit() {
    asm volatile("cp.async.commit_group;\n" ::);
}
__device__ __forceinline__ void ldsm_x4(uint32_t* r, uint32_t addr) {
    asm volatile("ldmatrix.sync.aligned.m8n8.x4.shared.b16 {%0,%1,%2,%3}, [%4];\n"
                 : "=r"(r[0]), "=r"(r[1]), "=r"(r[2]), "=r"(r[3]) : "r"(addr));
}
__device__ __forceinline__ void ldsm_x4t(uint32_t* r, uint32_t addr) {
    asm volatile("ldmatrix.sync.aligned.m8n8.x4.trans.shared.b16 {%0,%1,%2,%3}, [%4];\n"
                 : "=r"(r[0]), "=r"(r[1]), "=r"(r[2]), "=r"(r[3]) : "r"(addr));
}
__device__ __forceinline__ void mma16816(float* c, const uint32_t* a, uint32_t b0, uint32_t b1) {
    asm volatile("mma.sync.aligned.m16n8k16.row.col.f32.f16.f16.f32 "
                 "{%0,%1,%2,%3}, {%4,%5,%6,%7}, {%8,%9}, {%0,%1,%2,%3};\n"
                 : "+f"(c[0]), "+f"(c[1]), "+f"(c[2]), "+f"(c[3])
                 : "r"(a[0]), "r"(a[1]), "r"(a[2]), "r"(a[3]), "r"(b0), "r"(b1));
}

__device__ __forceinline__ float fexp(float x)  { return __expf(x); }
__device__ __forceinline__ float flog(float x)  { return __logf(x); }
__device__ __forceinline__ float ftanh(float x) {
    float e = __expf(2.0f * x);
    return 1.0f - 2.0f / (e + 1.0f);
}

// A-tile smem addressing: 2 rows per 128B line; conflict-free for ldsm + stores
__device__ __forceinline__ uint32_t a_addr(uint32_t base, int row, int c4) {
    int slot = ((row & 1) * 4) + ((c4 ^ ((row >> 1) & 3)) & 3);
    return base + (row >> 1) * 128 + slot * 16;
}

// ---------------- conversion / packing kernels --------------------------------
__global__ void convert_x(const float* __restrict__ x, __half* __restrict__ o)
{
    size_t g = (size_t)blockIdx.x * blockDim.x + threadIdx.x;
    const size_t total = (size_t)B_ROWS * (KP0 / 8);
    if (g >= total) return;
    int m  = (int)(g / (KP0 / 8));
    int k0 = (int)(g - (size_t)m * (KP0 / 8)) * 8;
    __half h[8];
    if (k0 + 8 <= S_DIM) {
        const float4* src = reinterpret_cast<const float4*>(x + (size_t)m * S_DIM + k0);
        float4 a = src[0], b = src[1];
        h[0]=__float2half(a.x); h[1]=__float2half(a.y);
        h[2]=__float2half(a.z); h[3]=__float2half(a.w);
        h[4]=__float2half(b.x); h[5]=__float2half(b.y);
        h[6]=__float2half(b.z); h[7]=__float2half(b.w);
    } else {
#pragma unroll
        for (int i = 0; i < 8; i++) h[i] = __float2half(0.0f);
    }
    *reinterpret_cast<uint4*>(o + (size_t)m * KP0 + k0) = *reinterpret_cast<uint4*>(h);
}

#define W1_ELEMS (KP0 * NB1)
#define W2_ELEMS (NB1 * NB2)
#define WH_ELEMS (KP2 * NB3)
__global__ void prep_weights(
    const float* __restrict__ W1,  const float* __restrict__ W2,
    const float* __restrict__ Wmu, const float* __restrict__ bmu,
    const float* __restrict__ Wlv, const float* __restrict__ blv,
    const float* __restrict__ Wu,  const float* __restrict__ bu,
    const float* __restrict__ Ww,  const float* __restrict__ bw,
    const float* __restrict__ Wb,  const float* __restrict__ bb)
{
    int idx = blockIdx.x * blockDim.x + threadIdx.x;
    if (idx < W1_ELEMS) {
        int k = idx / NB1, n = idx - k * NB1;
        g_W1[idx] = __float2half((k < S_DIM && n < H1_DIM) ? W1[(size_t)k * H1_DIM + n] : 0.0f);
    }
    int i2 = idx - W1_ELEMS;
    if (i2 >= 0 && i2 < W2_ELEMS) {
        int k = i2 / NB2, n = i2 - k * NB2;
        g_W2[i2] = __float2half((k < H1_DIM && n < H2_DIM) ? W2[(size_t)k * H2_DIM + n] : 0.0f);
    }
    int i3 = idx - (W1_ELEMS + W2_ELEMS);
    if (i3 >= 0 && i3 < WH_ELEMS) {
        int k = i3 / NB3, c = i3 - k * NB3;
        float v = 0.0f;
        if (k < H2_DIM) {
            if      (c < 17)  v = Wmu[k * 17  + c];
            else if (c < 34)  v = Wlv[k * 17  + (c - 17)];
            else if (c < 289) v = Wu [k * 255 + (c - 34)];
            else if (c < 544) v = Ww [k * 255 + (c - 289)];
            else if (c < 559) v = Wb [k * 15  + (c - 544)];
        }
        g_Wh[i3] = __float2half(v);
    }
    if (idx < HEAD_N) {
        int c = idx;
        float v;
        if      (c < 17)  v = bmu[c];
        else if (c < 34)  v = blv[c - 17];
        else if (c < 289) v = bu [c - 34];
        else if (c < 544) v = bw [c - 289];
        else              v = bb [c - 544];
        g_bh[c] = v;
    }
}

// ---------------- tensor-core GEMM (mma.sync fp16) ----------------------------
// Block tile 256(M) x (NG*8)(N) x 32(K); 128 threads = 4 warps, warp tile 64xN.
// NG is compile-time. Full tiles (NG=8) and the ragged last tile (NG_LAST)
// run in ONE launch, dispatched by a uniform top-level branch on blockIdx.x.
#define STAGES 5
#define A_BYTES 16384
#define STAGE_BYTES 20480

template <int OUT, int NG>
__device__ __forceinline__ void gemm_body(
    const __half* __restrict__ A, int lda, int Kiter,
    const __half* __restrict__ B, int ldb,
    const float* __restrict__ bias, int N,
    __half* __restrict__ Ch, int ldc, int n0, uint32_t sb)
{
    const int tid  = threadIdx.x;
    const int lane = tid & 31;
    const int wid  = tid >> 5;
    const int m0   = blockIdx.y * 256;
    const int KT   = Kiter / 32;

    float acc[4][NG][4];
#pragma unroll
    for (int i = 0; i < 4; i++)
#pragma unroll
        for (int j = 0; j < NG; j++)
#pragma unroll
            for (int q = 0; q < 4; q++) acc[i][j][q] = 0.0f;

    auto load_stage = [&](int s, int kt) {
        const uint32_t stA = sb + s * STAGE_BYTES;
        const uint32_t stB = stA + A_BYTES;
#pragma unroll
        for (int q = 0; q < 8; q++) {
            int g   = tid + 128 * q;
            int row = g >> 2;
            int c4  = g & 3;
            const __half* src = A + (size_t)(m0 + row) * lda + kt * 32 + c4 * 8;
            cp16(a_addr(stA, row, c4), src);
        }
#pragma unroll
        for (int q = 0; q < 2; q++) {
            int g   = tid + 128 * q;
            int row = g >> 3;
            int c8  = g & 7;
            if (c8 < NG) {   // compile-time
                const __half* src = B + (size_t)(kt * 32 + row) * ldb + n0 + c8 * 8;
                cp16(stB + row * 128 + ((c8 ^ (row & 7)) * 16), src);
            }
        }
        cp_commit();
    };

    load_stage(0, 0);
    load_stage(1, 1);
    load_stage(2, 2);
    load_stage(3, 3);

    int sc = 0, sp = 4;
    for (int c = 0; c < KT; c++) {
        asm volatile("cp.async.wait_group 3;" ::: "memory");
        __syncthreads();

        if (c + 4 < KT) load_stage(sp, c + 4);
        else            cp_commit();
        if (++sp == STAGES) sp = 0;

        const uint32_t stA = sb + sc * STAGE_BYTES;
        const uint32_t stB = stA + A_BYTES;
        if (++sc == STAGES) sc = 0;

#pragma unroll
        for (int kk = 0; kk < 2; kk++) {
            uint32_t ah[4][4], bh[(NG + 1) / 2][4];
            {
                int rbase = lane & 15;
                int q     = kk * 2 + (lane >> 4);
#pragma unroll
                for (int mi = 0; mi < 4; mi++) {
                    int r = wid * 64 + mi * 16 + rbase;
                    ldsm_x4(ah[mi], a_addr(stA, r, q));
                }
            }
            {
                int row  = kk * 16 + (lane & 15);
                int half = (lane >> 4);
#pragma unroll
                for (int nb = 0; nb < (NG + 1) / 2; nb++) {
                    int c8 = nb * 2 + half;   // NG even: always < NG
                    ldsm_x4t(bh[nb], stB + row * 128 + ((c8 ^ (row & 7)) * 16));
                }
            }
#pragma unroll
            for (int mi = 0; mi < 4; mi++) {
#pragma unroll
                for (int n8 = 0; n8 < NG; n8++) {
                    int nb = n8 >> 1, j = (n8 & 1) * 2;
                    mma16816(acc[mi][n8], ah[mi], bh[nb][j], bh[nb][j + 1]);
                }
            }
        }
    }

    // ---- epilogue ----
    const int lr = lane >> 2;
    const int lc = (lane & 3) * 2;
#pragma unroll
    for (int mi = 0; mi < 4; mi++) {
#pragma unroll
        for (int n8 = 0; n8 < NG; n8++) {
            int col = n0 + n8 * 8 + lc;
            float b0 = (col     < N) ? bias[col]     : 0.0f;
            float b1 = (col + 1 < N) ? bias[col + 1] : 0.0f;
#pragma unroll
            for (int h = 0; h < 2; h++) {
                int row = m0 + wid * 64 + mi * 16 + h * 8 + lr;
                float v0 = acc[mi][n8][2 * h + 0] + b0;
                float v1 = acc[mi][n8][2 * h + 1] + b1;
                __half2 hv;
                if (OUT == 1) {
                    v0 = (col     < N) ? fmaxf(v0, 0.0f) : 0.0f;
                    v1 = (col + 1 < N) ? fmaxf(v1, 0.0f) : 0.0f;
                    hv.x = __float2half(v0); hv.y = __float2half(v1);
                    *reinterpret_cast<__half2*>(&Ch[(size_t)row * ldc + col]) = hv;
                } else {
                    hv.x = __float2half(v0); hv.y = __float2half(v1);
                    size_t idx = ((size_t)(col >> 3) * B_ROWS + row) * 8 + (col & 7);
                    *reinterpret_cast<__half2*>(&Ch[idx]) = hv;
                }
            }
        }
    }
}

template <int OUT, int NG_LAST>
__global__ __launch_bounds__(128, 2) void gemm_mma(
    const __half* __restrict__ A, int lda, int Kiter,
    const __half* __restrict__ B, int ldb,
    const float* __restrict__ bias, int N,
    __half* __restrict__ Ch, int ldc)
{
    extern __shared__ char smem[];
    const uint32_t sb = smem_u32(smem);
    const int n0 = blockIdx.x * 64;
    if (NG_LAST != 0 && blockIdx.x == gridDim.x - 1) {
        gemm_body<OUT, NG_LAST>(A, lda, Kiter, B, ldb, bias, N, Ch, ldc, n0, sb);
    } else {
        gemm_body<OUT, 8>(A, lda, Kiter, B, ldb, bias, N, Ch, ldc, n0, sb);
    }
}

// ---------------- flow: one THREAD per batch row -------------------------------
__device__ __forceinline__ float h3grp(const uint4* G, int off) {
    const __half* h = reinterpret_cast<const __half*>(G);
    return __half2float(h[off]);
}

__global__ __launch_bounds__(256) void flow_kernel(
    const float* __restrict__ eps, float* __restrict__ out)
{
    __shared__ float sbuf[256 * A_DIM];
    const int tid = threadIdx.x;
    const size_t row = (size_t)blockIdx.x * 256 + tid;

    {
        const float* src = eps + (size_t)blockIdx.x * 256 * A_DIM;
#pragma unroll 4
        for (int i = tid; i < 256 * A_DIM; i += 256) sbuf[i] = src[i];
    }
    __syncthreads();

    float e[A_DIM];
#pragma unroll
    for (int a = 0; a < A_DIM; a++) e[a] = sbuf[tid * A_DIM + a];

    auto ldg8 = [&](int g) -> uint4 {
        return *reinterpret_cast<const uint4*>(g_h3 + ((size_t)g * B_ROWS + row) * 8);
    };

    float z[A_DIM];
    float lp = 0.0f;
    {
        uint4 G[5];
#pragma unroll
        for (int g = 0; g < 5; g++) G[g] = ldg8(g);
#pragma unroll
        for (int a = 0; a < A_DIM; a++) {
            float mu = ftanh(h3grp(G, a));
            float lv = ftanh(h3grp(G, 17 + a));
            z[a] = mu + fexp(lv) * e[a];
            lp += -0.5f * e[a] * e[a] - lv;
        }
    }

    float ldj = 0.0f;
#pragma unroll
    for (int k = 0; k < K_FLOWS; k++) {
        const int bu = 34 + 17 * k;
        const int bw = 289 + 17 * k;
        const int gu0 = bu >> 3, ou = bu & 7;
        const int gw0 = bw >> 3, ow = bw & 7;
        uint4 GU[3], GW[3];
#pragma unroll
        for (int g = 0; g < 3; g++) { GU[g] = ldg8(gu0 + g); GW[g] = ldg8(gw0 + g); }

        float uw = 0.0f, wns = 0.0f, wz = 0.0f;
#pragma unroll
        for (int a = 0; a < A_DIM; a++) {
            float u = h3grp(GU, ou + a);
            float w = h3grp(GW, ow + a);
            uw  = fmaf(w, u, uw);
            wns = fmaf(w, w, wns);
            wz  = fmaf(w, z[a], wz);
        }
        const int cb = 544 + k;
        float bk = __half2float(g_h3[((size_t)(cb >> 3) * B_ROWS + row) * 8 + (cb & 7)]);

        float sp    = fmaxf(uw, 0.0f) + flog(1.0f + fexp(-fabsf(uw)));
        float m_uw  = -1.0f + sp;
        float scale = (m_uw - uw) / wns;
        float t     = ftanh(wz + bk);
#pragma unroll
        for (int a = 0; a < A_DIM; a++) {
            float u = h3grp(GU, ou + a);
            float w = h3grp(GW, ow + a);
            z[a] = fmaf(fmaf(scale, w, u), t, z[a]);
        }
        float psi_u = m_uw * (1.0f - t * t);
        ldj += flog(fabsf(1.0f + psi_u));
    }

    __syncthreads();
#pragma unroll
    for (int a = 0; a < A_DIM; a++) sbuf[tid * A_DIM + a] = z[a];
    __syncthreads();
    {
        float* dst = out + (size_t)blockIdx.x * 256 * A_DIM;
#pragma unroll 4
        for (int i = tid; i < 256 * A_DIM; i += 256) dst[i] = sbuf[i];
    }

    lp -= 0.5f * (float)A_DIM * 1.8378770664093453f;
    float lpf = lp - ldj;
    out[(size_t)B_ROWS * A_DIM + row]          = fexp(lpf);
    out[(size_t)B_ROWS * A_DIM + B_ROWS + row] = lpf;
}

// ---------------- launch ------------------------------------------------------
extern "C" void kernel_launch(void* const* d_in, const int* in_sizes, int n_in,
                              void* d_out, int out_size)
{
    (void)in_sizes; (void)n_in; (void)out_size;

    const float* x   = (const float*)d_in[0];
    const float* eps = (const float*)d_in[1];
    const float* W1  = (const float*)d_in[2];
    const float* b1  = (const float*)d_in[3];
    const float* W2  = (const float*)d_in[4];
    const float* b2  = (const float*)d_in[5];
    const float* Wmu = (const float*)d_in[6];
    const float* bmu = (const float*)d_in[7];
    const float* Wlv = (const float*)d_in[8];
    const float* blv = (const float*)d_in[9];
    const float* Wu  = (const float*)d_in[10];
    const float* bu  = (const float*)d_in[11];
    const float* Ww  = (const float*)d_in[12];
    const float* bw  = (const float*)d_in[13];
    const float* Wb  = (const float*)d_in[14];
    const float* bb  = (const float*)d_in[15];
    float* out = (float*)d_out;

    __half *x16, *h1, *h2, *h3, *w1, *w2, *wh;
    float *bhp;
    cudaGetSymbolAddress((void**)&x16, g_x16);
    cudaGetSymbolAddress((void**)&h1,  g_h1);
    cudaGetSymbolAddress((void**)&h2,  g_h2);
    cudaGetSymbolAddress((void**)&h3,  g_h3);
    cudaGetSymbolAddress((void**)&w1,  g_W1);
    cudaGetSymbolAddress((void**)&w2,  g_W2);
    cudaGetSymbolAddress((void**)&wh,  g_Wh);
    cudaGetSymbolAddress((void**)&bhp, g_bh);

    convert_x<<<(int)(((size_t)B_ROWS * (KP0 / 8) + 255) / 256), 256>>>(x, x16);
    const int prep_total = W1_ELEMS + W2_ELEMS + WH_ELEMS;
    prep_weights<<<(prep_total + 255) / 256, 256>>>(W1, W2, Wmu, bmu, Wlv, blv,
                                                    Wu, bu, Ww, bw, Wb, bb);

    const int smem_bytes = STAGES * STAGE_BYTES;   // 102400
    cudaFuncSetAttribute(gemm_mma<1, 2>, cudaFuncAttributeMaxDynamicSharedMemorySize, smem_bytes);
    cudaFuncSetAttribute(gemm_mma<1, 6>, cudaFuncAttributeMaxDynamicSharedMemorySize, smem_bytes);
    cudaFuncSetAttribute(gemm_mma<0, 6>, cudaFuncAttributeMaxDynamicSharedMemorySize, smem_bytes);

    dim3 blk(128);
    // layer 1: N=400 -> 6 full tiles + 1 x NG=2 (cols 384..399), one launch
    gemm_mma<1, 2><<<dim3(7, B_ROWS / 256), blk, smem_bytes>>>(
        x16, KP0, KP0, w1, NB1, b1, H1_DIM, h1, NB1);
    // layer 2: N=300 -> 4 full tiles + 1 x NG=6 (cols 256..303)
    gemm_mma<1, 6><<<dim3(5, B_ROWS / 256), blk, smem_bytes>>>(
        h1, NB1, KI1, w2, NB2, b2, H2_DIM, h2, NB2);
    // heads: N=559 -> 8 full tiles + 1 x NG=6 (cols 512..559)
    gemm_mma<0, 6><<<dim3(9, B_ROWS / 256), blk, smem_bytes>>>(
        h2, KP2, KP2, wh, NB3, bhp, HEAD_N, h3, NB3);

    flow_kernel<<<B_ROWS / 256, 256>>>(eps, out);
}

// round 15
// speedup vs baseline: 1.2651x; 1.0244x over previous
#include <cuda_runtime.h>
#include <cuda_fp16.h>
#include <math.h>
#include <stdint.h>

#define B_ROWS 65536
#define S_DIM  376
#define A_DIM  17
#define H1_DIM 400
#define H2_DIM 300
#define K_FLOWS 15
#define HEAD_N 559

#define KP0 384
#define NB1 448
#define KI1 416
#define NB2 320
#define KP2 320
#define NB3 576

// ---------------- scratch (static device globals; no allocation) -------------
// device globals are zero-initialized; padding columns never written stay 0
__device__ __half g_x16[(size_t)B_ROWS * KP0];
__device__ __half g_h1[(size_t)B_ROWS * NB1];
__device__ __half g_h2[(size_t)B_ROWS * NB2];
// heads, interleaved-by-8: element (row, col) at [ (col/8)*B_ROWS*8 + row*8 + col%8 ]
__device__ __half g_h3[(size_t)B_ROWS * NB3];

__device__ __half g_W1[KP0 * NB1];
__device__ __half g_W2[NB1 * NB2];
__device__ __half g_Wh[KP2 * NB3];
__device__ float  g_bh[HEAD_N];

// ---------------- small helpers ----------------------------------------------
__device__ __forceinline__ uint32_t smem_u32(const void* p) {
    return (uint32_t)__cvta_generic_to_shared(p);
}
__device__ __forceinline__ void cp16(uint32_t dst, const void* src) {
    asm volatile("cp.async.cg.shared.global [%0], [%1], 16;\n" :: "r"(dst), "l"(src));
}
__device__ __forceinline__ void cp_commit() {
    asm volatile("cp.async.commit_group;\n" ::);
}
__device__ __forceinline__ void ldsm_x4(uint32_t* r, uint32_t addr) {
    asm volatile("ldmatrix.sync.aligned.m8n8.x4.shared.b16 {%0,%1,%2,%3}, [%4];\n"
                 : "=r"(r[0]), "=r"(r[1]), "=r"(r[2]), "=r"(r[3]) : "r"(addr));
}
__device__ __forceinline__ void ldsm_x4t(uint32_t* r, uint32_t addr) {
    asm volatile("ldmatrix.sync.aligned.m8n8.x4.trans.shared.b16 {%0,%1,%2,%3}, [%4];\n"
                 : "=r"(r[0]), "=r"(r[1]), "=r"(r[2]), "=r"(r[3]) : "r"(addr));
}
__device__ __forceinline__ void mma16816(float* c, const uint32_t* a, uint32_t b0, uint32_t b1) {
    asm volatile("mma.sync.aligned.m16n8k16.row.col.f32.f16.f16.f32 "
                 "{%0,%1,%2,%3}, {%4,%5,%6,%7}, {%8,%9}, {%0,%1,%2,%3};\n"
                 : "+f"(c[0]), "+f"(c[1]), "+f"(c[2]), "+f"(c[3])
                 : "r"(a[0]), "r"(a[1]), "r"(a[2]), "r"(a[3]), "r"(b0), "r"(b1));
}

__device__ __forceinline__ float fexp(float x)  { return __expf(x); }
__device__ __forceinline__ float flog(float x)  { return __logf(x); }
__device__ __forceinline__ float ftanh(float x) {
    float e = __expf(2.0f * x);
    return 1.0f - 2.0f / (e + 1.0f);
}

// A-tile smem addressing: 2 rows per 128B line; conflict-free for ldsm + stores
__device__ __forceinline__ uint32_t a_addr(uint32_t base, int row, int c4) {
    int slot = ((row & 1) * 4) + ((c4 ^ ((row >> 1) & 3)) & 3);
    return base + (row >> 1) * 128 + slot * 16;
}

// ---------------- conversion / packing kernels --------------------------------
__global__ void convert_x(const float* __restrict__ x, __half* __restrict__ o)
{
    size_t g = (size_t)blockIdx.x * blockDim.x + threadIdx.x;
    const size_t total = (size_t)B_ROWS * (KP0 / 8);
    if (g >= total) return;
    int m  = (int)(g / (KP0 / 8));
    int k0 = (int)(g - (size_t)m * (KP0 / 8)) * 8;
    __half h[8];
    if (k0 + 8 <= S_DIM) {
        const float4* src = reinterpret_cast<const float4*>(x + (size_t)m * S_DIM + k0);
        float4 a = src[0], b = src[1];
        h[0]=__float2half(a.x); h[1]=__float2half(a.y);
        h[2]=__float2half(a.z); h[3]=__float2half(a.w);
        h[4]=__float2half(b.x); h[5]=__float2half(b.y);
        h[6]=__float2half(b.z); h[7]=__float2half(b.w);
    } else {
#pragma unroll
        for (int i = 0; i < 8; i++) h[i] = __float2half(0.0f);
    }
    *reinterpret_cast<uint4*>(o + (size_t)m * KP0 + k0) = *reinterpret_cast<uint4*>(h);
}

#define W1_ELEMS (KP0 * NB1)
#define W2_ELEMS (NB1 * NB2)
#define WH_ELEMS (KP2 * NB3)
__global__ void prep_weights(
    const float* __restrict__ W1,  const float* __restrict__ W2,
    const float* __restrict__ Wmu, const float* __restrict__ bmu,
    const float* __restrict__ Wlv, const float* __restrict__ blv,
    const float* __restrict__ Wu,  const float* __restrict__ bu,
    const float* __restrict__ Ww,  const float* __restrict__ bw,
    const float* __restrict__ Wb,  const float* __restrict__ bb)
{
    int idx = blockIdx.x * blockDim.x + threadIdx.x;
    if (idx < W1_ELEMS) {
        int k = idx / NB1, n = idx - k * NB1;
        g_W1[idx] = __float2half((k < S_DIM && n < H1_DIM) ? W1[(size_t)k * H1_DIM + n] : 0.0f);
    }
    int i2 = idx - W1_ELEMS;
    if (i2 >= 0 && i2 < W2_ELEMS) {
        int k = i2 / NB2, n = i2 - k * NB2;
        g_W2[i2] = __float2half((k < H1_DIM && n < H2_DIM) ? W2[(size_t)k * H2_DIM + n] : 0.0f);
    }
    int i3 = idx - (W1_ELEMS + W2_ELEMS);
    if (i3 >= 0 && i3 < WH_ELEMS) {
        int k = i3 / NB3, c = i3 - k * NB3;
        float v = 0.0f;
        if (k < H2_DIM) {
            if      (c < 17)  v = Wmu[k * 17  + c];
            else if (c < 34)  v = Wlv[k * 17  + (c - 17)];
            else if (c < 289) v = Wu [k * 255 + (c - 34)];
            else if (c < 544) v = Ww [k * 255 + (c - 289)];
            else if (c < 559) v = Wb [k * 15  + (c - 544)];
        }
        g_Wh[i3] = __float2half(v);
    }
    if (idx < HEAD_N) {
        int c = idx;
        float v;
        if      (c < 17)  v = bmu[c];
        else if (c < 34)  v = blv[c - 17];
        else if (c < 289) v = bu [c - 34];
        else if (c < 544) v = bw [c - 289];
        else              v = bb [c - 544];
        g_bh[c] = v;
    }
}

// ---------------- tensor-core GEMM (mma.sync fp16) ----------------------------
// Block tile 256(M) x (NG*8)(N) x 32(K); 128 threads = 4 warps, warp tile 64xN.
// NG compile-time; ragged last N-tile handled by top-level uniform dispatch.
// KTAIL compile-time: last K-chunk executes kk=0 only (kk=1 half is all-zero
// padding), peeled AFTER the main loop so the hot loop codegen is untouched.
#define STAGES 5
#define A_BYTES 16384
#define STAGE_BYTES 20480

template <int OUT, int NG, bool KTAIL>
__device__ __forceinline__ void gemm_body(
    const __half* __restrict__ A, int lda, int Kiter,
    const __half* __restrict__ B, int ldb,
    const float* __restrict__ bias, int N,
    __half* __restrict__ Ch, int ldc, int n0, uint32_t sb)
{
    const int tid  = threadIdx.x;
    const int lane = tid & 31;
    const int wid  = tid >> 5;
    const int m0   = blockIdx.y * 256;
    const int KT   = Kiter / 32;
    const int KTm  = KTAIL ? KT - 1 : KT;

    float acc[4][NG][4];
#pragma unroll
    for (int i = 0; i < 4; i++)
#pragma unroll
        for (int j = 0; j < NG; j++)
#pragma unroll
            for (int q = 0; q < 4; q++) acc[i][j][q] = 0.0f;

    auto load_stage = [&](int s, int kt) {
        const uint32_t stA = sb + s * STAGE_BYTES;
        const uint32_t stB = stA + A_BYTES;
#pragma unroll
        for (int q = 0; q < 8; q++) {
            int g   = tid + 128 * q;
            int row = g >> 2;
            int c4  = g & 3;
            const __half* src = A + (size_t)(m0 + row) * lda + kt * 32 + c4 * 8;
            cp16(a_addr(stA, row, c4), src);
        }
#pragma unroll
        for (int q = 0; q < 2; q++) {
            int g   = tid + 128 * q;
            int row = g >> 3;
            int c8  = g & 7;
            if (c8 < NG) {
                const __half* src = B + (size_t)(kt * 32 + row) * ldb + n0 + c8 * 8;
                cp16(stB + row * 128 + ((c8 ^ (row & 7)) * 16), src);
            }
        }
        cp_commit();
    };

    auto consume_kk = [&](uint32_t stA, uint32_t stB, int kk) {
        uint32_t ah[4][4], bh[(NG + 1) / 2][4];
        {
            int rbase = lane & 15;
            int q     = kk * 2 + (lane >> 4);
#pragma unroll
            for (int mi = 0; mi < 4; mi++) {
                int r = wid * 64 + mi * 16 + rbase;
                ldsm_x4(ah[mi], a_addr(stA, r, q));
            }
        }
        {
            int row  = kk * 16 + (lane & 15);
            int half = (lane >> 4);
#pragma unroll
            for (int nb = 0; nb < (NG + 1) / 2; nb++) {
                int c8 = nb * 2 + half;   // NG even: always < NG
                ldsm_x4t(bh[nb], stB + row * 128 + ((c8 ^ (row & 7)) * 16));
            }
        }
#pragma unroll
        for (int mi = 0; mi < 4; mi++) {
#pragma unroll
            for (int n8 = 0; n8 < NG; n8++) {
                int nb = n8 >> 1, j = (n8 & 1) * 2;
                mma16816(acc[mi][n8], ah[mi], bh[nb][j], bh[nb][j + 1]);
            }
        }
    };

    load_stage(0, 0);
    load_stage(1, 1);
    load_stage(2, 2);
    load_stage(3, 3);

    int sc = 0, sp = 4;
    for (int c = 0; c < KTm; c++) {
        asm volatile("cp.async.wait_group 3;" ::: "memory");
        __syncthreads();

        if (c + 4 < KT) load_stage(sp, c + 4);
        else            cp_commit();
        if (++sp == STAGES) sp = 0;

        const uint32_t stA = sb + sc * STAGE_BYTES;
        const uint32_t stB = stA + A_BYTES;
        if (++sc == STAGES) sc = 0;

        consume_kk(stA, stB, 0);
        consume_kk(stA, stB, 1);
    }

    if (KTAIL) {
        // last chunk: kk=1 half is all-zero padding in A and B -> skip it
        asm volatile("cp.async.wait_group 0;" ::: "memory");
        __syncthreads();
        const uint32_t stA = sb + sc * STAGE_BYTES;
        const uint32_t stB = stA + A_BYTES;
        consume_kk(stA, stB, 0);
    }

    // ---- epilogue ----
    const int lr = lane >> 2;
    const int lc = (lane & 3) * 2;
#pragma unroll
    for (int mi = 0; mi < 4; mi++) {
#pragma unroll
        for (int n8 = 0; n8 < NG; n8++) {
            int col = n0 + n8 * 8 + lc;
            float b0 = (col     < N) ? bias[col]     : 0.0f;
            float b1 = (col + 1 < N) ? bias[col + 1] : 0.0f;
#pragma unroll
            for (int h = 0; h < 2; h++) {
                int row = m0 + wid * 64 + mi * 16 + h * 8 + lr;
                float v0 = acc[mi][n8][2 * h + 0] + b0;
                float v1 = acc[mi][n8][2 * h + 1] + b1;
                __half2 hv;
                if (OUT == 1) {
                    v0 = (col     < N) ? fmaxf(v0, 0.0f) : 0.0f;
                    v1 = (col + 1 < N) ? fmaxf(v1, 0.0f) : 0.0f;
                    hv.x = __float2half(v0); hv.y = __float2half(v1);
                    *reinterpret_cast<__half2*>(&Ch[(size_t)row * ldc + col]) = hv;
                } else {
                    hv.x = __float2half(v0); hv.y = __float2half(v1);
                    size_t idx = ((size_t)(col >> 3) * B_ROWS + row) * 8 + (col & 7);
                    *reinterpret_cast<__half2*>(&Ch[idx]) = hv;
                }
            }
        }
    }
}

template <int OUT, int NG_LAST, bool KTAIL>
__global__ __launch_bounds__(128, 2) void gemm_mma(
    const __half* __restrict__ A, int lda, int Kiter,
    const __half* __restrict__ B, int ldb,
    const float* __restrict__ bias, int N,
    __half* __restrict__ Ch, int ldc)
{
    extern __shared__ char smem[];
    const uint32_t sb = smem_u32(smem);
    const int n0 = blockIdx.x * 64;
    if (NG_LAST != 0 && blockIdx.x == gridDim.x - 1) {
        gemm_body<OUT, NG_LAST, KTAIL>(A, lda, Kiter, B, ldb, bias, N, Ch, ldc, n0, sb);
    } else {
        gemm_body<OUT, 8, KTAIL>(A, lda, Kiter, B, ldb, bias, N, Ch, ldc, n0, sb);
    }
}

// ---------------- flow: one THREAD per batch row -------------------------------
__device__ __forceinline__ float h3grp(const uint4* G, int off) {
    const __half* h = reinterpret_cast<const __half*>(G);
    return __half2float(h[off]);
}

__global__ __launch_bounds__(256) void flow_kernel(
    const float* __restrict__ eps, float* __restrict__ out)
{
    __shared__ float sbuf[256 * A_DIM];
    const int tid = threadIdx.x;
    const size_t row = (size_t)blockIdx.x * 256 + tid;

    {
        const float* src = eps + (size_t)blockIdx.x * 256 * A_DIM;
#pragma unroll 4
        for (int i = tid; i < 256 * A_DIM; i += 256) sbuf[i] = src[i];
    }
    __syncthreads();

    float e[A_DIM];
#pragma unroll
    for (int a = 0; a < A_DIM; a++) e[a] = sbuf[tid * A_DIM + a];

    auto ldg8 = [&](int g) -> uint4 {
        return *reinterpret_cast<const uint4*>(g_h3 + ((size_t)g * B_ROWS + row) * 8);
    };

    float z[A_DIM];
    float lp = 0.0f;
    {
        uint4 G[5];
#pragma unroll
        for (int g = 0; g < 5; g++) G[g] = ldg8(g);
#pragma unroll
        for (int a = 0; a < A_DIM; a++) {
            float mu = ftanh(h3grp(G, a));
            float lv = ftanh(h3grp(G, 17 + a));
            z[a] = mu + fexp(lv) * e[a];
            lp += -0.5f * e[a] * e[a] - lv;
        }
    }

    // preload all 15 flow biases (cols 544..558 live in groups 68,69)
    uint4 GB[2];
    GB[0] = ldg8(68);
    GB[1] = ldg8(69);

    float ldj = 0.0f;
#pragma unroll
    for (int k = 0; k < K_FLOWS; k++) {
        const int bu = 34 + 17 * k;
        const int bw = 289 + 17 * k;
        const int gu0 = bu >> 3, ou = bu & 7;
        const int gw0 = bw >> 3, ow = bw & 7;
        uint4 GU[3], GW[3];
#pragma unroll
        for (int g = 0; g < 3; g++) { GU[g] = ldg8(gu0 + g); GW[g] = ldg8(gw0 + g); }

        float uw = 0.0f, wns = 0.0f, wz = 0.0f;
#pragma unroll
        for (int a = 0; a < A_DIM; a++) {
            float u = h3grp(GU, ou + a);
            float w = h3grp(GW, ow + a);
            uw  = fmaf(w, u, uw);
            wns = fmaf(w, w, wns);
            wz  = fmaf(w, z[a], wz);
        }
        float bk = h3grp(GB, k);

        float sp    = fmaxf(uw, 0.0f) + flog(1.0f + fexp(-fabsf(uw)));
        float m_uw  = -1.0f + sp;
        float scale = (m_uw - uw) / wns;
        float t     = ftanh(wz + bk);
#pragma unroll
        for (int a = 0; a < A_DIM; a++) {
            float u = h3grp(GU, ou + a);
            float w = h3grp(GW, ow + a);
            z[a] = fmaf(fmaf(scale, w, u), t, z[a]);
        }
        float psi_u = m_uw * (1.0f - t * t);
        ldj += flog(fabsf(1.0f + psi_u));
    }

    __syncthreads();
#pragma unroll
    for (int a = 0; a < A_DIM; a++) sbuf[tid * A_DIM + a] = z[a];
    __syncthreads();
    {
        float* dst = out + (size_t)blockIdx.x * 256 * A_DIM;
#pragma unroll 4
        for (int i = tid; i < 256 * A_DIM; i += 256) dst[i] = sbuf[i];
    }

    lp -= 0.5f * (float)A_DIM * 1.8378770664093453f;
    float lpf = lp - ldj;
    out[(size_t)B_ROWS * A_DIM + row]          = fexp(lpf);
    out[(size_t)B_ROWS * A_DIM + B_ROWS + row] = lpf;
}

// ---------------- launch ------------------------------------------------------
extern "C" void kernel_launch(void* const* d_in, const int* in_sizes, int n_in,
                              void* d_out, int out_size)
{
    (void)in_sizes; (void)n_in; (void)out_size;

    const float* x   = (const float*)d_in[0];
    const float* eps = (const float*)d_in[1];
    const float* W1  = (const float*)d_in[2];
    const float* b1  = (const float*)d_in[3];
    const float* W2  = (const float*)d_in[4];
    const float* b2  = (const float*)d_in[5];
    const float* Wmu = (const float*)d_in[6];
    const float* bmu = (const float*)d_in[7];
    const float* Wlv = (const float*)d_in[8];
    const float* blv = (const float*)d_in[9];
    const float* Wu  = (const float*)d_in[10];
    const float* bu  = (const float*)d_in[11];
    const float* Ww  = (const float*)d_in[12];
    const float* bw  = (const float*)d_in[13];
    const float* Wb  = (const float*)d_in[14];
    const float* bb  = (const float*)d_in[15];
    float* out = (float*)d_out;

    __half *x16, *h1, *h2, *h3, *w1, *w2, *wh;
    float *bhp;
    cudaGetSymbolAddress((void**)&x16, g_x16);
    cudaGetSymbolAddress((void**)&h1,  g_h1);
    cudaGetSymbolAddress((void**)&h2,  g_h2);
    cudaGetSymbolAddress((void**)&h3,  g_h3);
    cudaGetSymbolAddress((void**)&w1,  g_W1);
    cudaGetSymbolAddress((void**)&w2,  g_W2);
    cudaGetSymbolAddress((void**)&wh,  g_Wh);
    cudaGetSymbolAddress((void**)&bhp, g_bh);

    convert_x<<<(int)(((size_t)B_ROWS * (KP0 / 8) + 255) / 256), 256>>>(x, x16);
    const int prep_total = W1_ELEMS + W2_ELEMS + WH_ELEMS;
    prep_weights<<<(prep_total + 255) / 256, 256>>>(W1, W2, Wmu, bmu, Wlv, blv,
                                                    Wu, bu, Ww, bw, Wb, bb);

    const int smem_bytes = STAGES * STAGE_BYTES;   // 102400
    cudaFuncSetAttribute((const void*)gemm_mma<1, 2, false>, cudaFuncAttributeMaxDynamicSharedMemorySize, smem_bytes);
    cudaFuncSetAttribute((const void*)gemm_mma<1, 6, true>,  cudaFuncAttributeMaxDynamicSharedMemorySize, smem_bytes);
    cudaFuncSetAttribute((const void*)gemm_mma<0, 6, true>,  cudaFuncAttributeMaxDynamicSharedMemorySize, smem_bytes);

    dim3 blk(128);
    // layer 1: N=400 -> 6 full tiles + 1 x NG=2 (cols 384..399); no K tail trim
    gemm_mma<1, 2, false><<<dim3(7, B_ROWS / 256), blk, smem_bytes>>>(
        x16, KP0, KP0, w1, NB1, b1, H1_DIM, h1, NB1);
    // layer 2: N=300 -> 4 full + NG=6; K=416, last chunk kk=1 (cols 400-415) zero
    gemm_mma<1, 6, true><<<dim3(5, B_ROWS / 256), blk, smem_bytes>>>(
        h1, NB1, KI1, w2, NB2, b2, H2_DIM, h2, NB2);
    // heads: N=559 -> 8 full + NG=6; K=320, last chunk kk=1 (cols 304-319) zero
    gemm_mma<0, 6, true><<<dim3(9, B_ROWS / 256), blk, smem_bytes>>>(
        h2, KP2, KP2, wh, NB3, bhp, HEAD_N, h3, NB3);

    flow_kernel<<<B_ROWS / 256, 256>>>(eps, out);
}

// round 16
// speedup vs baseline: 1.3756x; 1.0873x over previous
#include <cuda_runtime.h>
#include <cuda_fp16.h>
#include <math.h>
#include <stdint.h>

#define B_ROWS 65536
#define S_DIM  376
#define A_DIM  17
#define H1_DIM 400
#define H2_DIM 300
#define K_FLOWS 15
#define HEAD_N 559

#define KP0 384
#define NB1 448
#define KI1 416
#define NB2 320
#define KP2 320
#define NB3 576

// ---------------- scratch (static device globals; no allocation) -------------
// device globals are zero-initialized; padding columns never written stay 0
__device__ __half g_x16[(size_t)B_ROWS * KP0];
__device__ __half g_h1[(size_t)B_ROWS * NB1];
__device__ __half g_h2[(size_t)B_ROWS * NB2];
// heads, interleaved-by-8: element (row, col) at [ (col/8)*B_ROWS*8 + row*8 + col%8 ]
__device__ __half g_h3[(size_t)B_ROWS * NB3];

__device__ __half g_W1[KP0 * NB1];
__device__ __half g_W2[NB1 * NB2];
__device__ __half g_Wh[KP2 * NB3];
__device__ float  g_bh[HEAD_N];

// ---------------- small helpers ----------------------------------------------
__device__ __forceinline__ uint32_t smem_u32(const void* p) {
    return (uint32_t)__cvta_generic_to_shared(p);
}
__device__ __forceinline__ void cp16(uint32_t dst, const void* src) {
    asm volatile("cp.async.cg.shared.global [%0], [%1], 16;\n" :: "r"(dst), "l"(src));
}
__device__ __forceinline__ void cp_commit() {
    asm volatile("cp.async.commit_group;\n" ::);
}
__device__ __forceinline__ void ldsm_x4(uint32_t* r, uint32_t addr) {
    asm volatile("ldmatrix.sync.aligned.m8n8.x4.shared.b16 {%0,%1,%2,%3}, [%4];\n"
                 : "=r"(r[0]), "=r"(r[1]), "=r"(r[2]), "=r"(r[3]) : "r"(addr));
}
__device__ __forceinline__ void ldsm_x4t(uint32_t* r, uint32_t addr) {
    asm volatile("ldmatrix.sync.aligned.m8n8.x4.trans.shared.b16 {%0,%1,%2,%3}, [%4];\n"
                 : "=r"(r[0]), "=r"(r[1]), "=r"(r[2]), "=r"(r[3]) : "r"(addr));
}
__device__ __forceinline__ void mma16816(float* c, const uint32_t* a, uint32_t b0, uint32_t b1) {
    asm volatile("mma.sync.aligned.m16n8k16.row.col.f32.f16.f16.f32 "
                 "{%0,%1,%2,%3}, {%4,%5,%6,%7}, {%8,%9}, {%0,%1,%2,%3};\n"
                 : "+f"(c[0]), "+f"(c[1]), "+f"(c[2]), "+f"(c[3])
                 : "r"(a[0]), "r"(a[1]), "r"(a[2]), "r"(a[3]), "r"(b0), "r"(b1));
}

__device__ __forceinline__ float fexp(float x)  { return __expf(x); }
__device__ __forceinline__ float flog(float x)  { return __logf(x); }
__device__ __forceinline__ float ftanh(float x) {
    float e = __expf(2.0f * x);
    return 1.0f - 2.0f / (e + 1.0f);
}

// A-tile smem addressing: 2 rows per 128B line; conflict-free for ldsm + stores
__device__ __forceinline__ uint32_t a_addr(uint32_t base, int row, int c4) {
    int slot = ((row & 1) * 4) + ((c4 ^ ((row >> 1) & 3)) & 3);
    return base + (row >> 1) * 128 + slot * 16;
}

// ---------------- conversion / packing kernels --------------------------------
__global__ void convert_x(const float* __restrict__ x, __half* __restrict__ o,
                          int m_base)
{
    size_t g = (size_t)blockIdx.x * blockDim.x + threadIdx.x;
    const size_t total = (size_t)(B_ROWS / 2) * (KP0 / 8);
    if (g >= total) return;
    int m  = m_base + (int)(g / (KP0 / 8));
    int k0 = (int)(g % (KP0 / 8)) * 8;
    __half h[8];
    if (k0 + 8 <= S_DIM) {
        const float4* src = reinterpret_cast<const float4*>(x + (size_t)m * S_DIM + k0);
        float4 a = src[0], b = src[1];
        h[0]=__float2half(a.x); h[1]=__float2half(a.y);
        h[2]=__float2half(a.z); h[3]=__float2half(a.w);
        h[4]=__float2half(b.x); h[5]=__float2half(b.y);
        h[6]=__float2half(b.z); h[7]=__float2half(b.w);
    } else {
#pragma unroll
        for (int i = 0; i < 8; i++) h[i] = __float2half(0.0f);
    }
    *reinterpret_cast<uint4*>(o + (size_t)m * KP0 + k0) = *reinterpret_cast<uint4*>(h);
}

#define W1_ELEMS (KP0 * NB1)
#define W2_ELEMS (NB1 * NB2)
#define WH_ELEMS (KP2 * NB3)
__global__ void prep_weights(
    const float* __restrict__ W1,  const float* __restrict__ W2,
    const float* __restrict__ Wmu, const float* __restrict__ bmu,
    const float* __restrict__ Wlv, const float* __restrict__ blv,
    const float* __restrict__ Wu,  const float* __restrict__ bu,
    const float* __restrict__ Ww,  const float* __restrict__ bw,
    const float* __restrict__ Wb,  const float* __restrict__ bb)
{
    int idx = blockIdx.x * blockDim.x + threadIdx.x;
    if (idx < W1_ELEMS) {
        int k = idx / NB1, n = idx - k * NB1;
        g_W1[idx] = __float2half((k < S_DIM && n < H1_DIM) ? W1[(size_t)k * H1_DIM + n] : 0.0f);
    }
    int i2 = idx - W1_ELEMS;
    if (i2 >= 0 && i2 < W2_ELEMS) {
        int k = i2 / NB2, n = i2 - k * NB2;
        g_W2[i2] = __float2half((k < H1_DIM && n < H2_DIM) ? W2[(size_t)k * H2_DIM + n] : 0.0f);
    }
    int i3 = idx - (W1_ELEMS + W2_ELEMS);
    if (i3 >= 0 && i3 < WH_ELEMS) {
        int k = i3 / NB3, c = i3 - k * NB3;
        float v = 0.0f;
        if (k < H2_DIM) {
            if      (c < 17)  v = Wmu[k * 17  + c];
            else if (c < 34)  v = Wlv[k * 17  + (c - 17)];
            else if (c < 289) v = Wu [k * 255 + (c - 34)];
            else if (c < 544) v = Ww [k * 255 + (c - 289)];
            else if (c < 559) v = Wb [k * 15  + (c - 544)];
        }
        g_Wh[i3] = __float2half(v);
    }
    if (idx < HEAD_N) {
        int c = idx;
        float v;
        if      (c < 17)  v = bmu[c];
        else if (c < 34)  v = blv[c - 17];
        else if (c < 289) v = bu [c - 34];
        else if (c < 544) v = bw [c - 289];
        else              v = bb [c - 544];
        g_bh[c] = v;
    }
}

// ---------------- tensor-core GEMM (mma.sync fp16) ----------------------------
// Block tile 256(M) x (NG*8)(N) x 32(K); 128 threads = 4 warps, warp tile 64xN.
// NG compile-time; ragged last N-tile via top-level uniform dispatch.
// KTAIL compile-time: last K-chunk executes kk=0 only (kk=1 is zero padding).
#define STAGES 5
#define A_BYTES 16384
#define STAGE_BYTES 20480

template <int OUT, int NG, bool KTAIL>
__device__ __forceinline__ void gemm_body(
    const __half* __restrict__ A, int lda, int Kiter,
    const __half* __restrict__ B, int ldb,
    const float* __restrict__ bias, int N,
    __half* __restrict__ Ch, int ldc, int n0, int m0, uint32_t sb)
{
    const int tid  = threadIdx.x;
    const int lane = tid & 31;
    const int wid  = tid >> 5;
    const int KT   = Kiter / 32;
    const int KTm  = KTAIL ? KT - 1 : KT;

    float acc[4][NG][4];
#pragma unroll
    for (int i = 0; i < 4; i++)
#pragma unroll
        for (int j = 0; j < NG; j++)
#pragma unroll
            for (int q = 0; q < 4; q++) acc[i][j][q] = 0.0f;

    auto load_stage = [&](int s, int kt) {
        const uint32_t stA = sb + s * STAGE_BYTES;
        const uint32_t stB = stA + A_BYTES;
#pragma unroll
        for (int q = 0; q < 8; q++) {
            int g   = tid + 128 * q;
            int row = g >> 2;
            int c4  = g & 3;
            const __half* src = A + (size_t)(m0 + row) * lda + kt * 32 + c4 * 8;
            cp16(a_addr(stA, row, c4), src);
        }
#pragma unroll
        for (int q = 0; q < 2; q++) {
            int g   = tid + 128 * q;
            int row = g >> 3;
            int c8  = g & 7;
            if (c8 < NG) {
                const __half* src = B + (size_t)(kt * 32 + row) * ldb + n0 + c8 * 8;
                cp16(stB + row * 128 + ((c8 ^ (row & 7)) * 16), src);
            }
        }
        cp_commit();
    };

    auto consume_kk = [&](uint32_t stA, uint32_t stB, int kk) {
        uint32_t ah[4][4], bh[(NG + 1) / 2][4];
        {
            int rbase = lane & 15;
            int q     = kk * 2 + (lane >> 4);
#pragma unroll
            for (int mi = 0; mi < 4; mi++) {
                int r = wid * 64 + mi * 16 + rbase;
                ldsm_x4(ah[mi], a_addr(stA, r, q));
            }
        }
        {
            int row  = kk * 16 + (lane & 15);
            int half = (lane >> 4);
#pragma unroll
            for (int nb = 0; nb < (NG + 1) / 2; nb++) {
                int c8 = nb * 2 + half;   // NG even: always < NG
                ldsm_x4t(bh[nb], stB + row * 128 + ((c8 ^ (row & 7)) * 16));
            }
        }
#pragma unroll
        for (int mi = 0; mi < 4; mi++) {
#pragma unroll
            for (int n8 = 0; n8 < NG; n8++) {
                int nb = n8 >> 1, j = (n8 & 1) * 2;
                mma16816(acc[mi][n8], ah[mi], bh[nb][j], bh[nb][j + 1]);
            }
        }
    };

    load_stage(0, 0);
    load_stage(1, 1);
    load_stage(2, 2);
    load_stage(3, 3);

    int sc = 0, sp = 4;
    for (int c = 0; c < KTm; c++) {
        asm volatile("cp.async.wait_group 3;" ::: "memory");
        __syncthreads();

        if (c + 4 < KT) load_stage(sp, c + 4);
        else            cp_commit();
        if (++sp == STAGES) sp = 0;

        const uint32_t stA = sb + sc * STAGE_BYTES;
        const uint32_t stB = stA + A_BYTES;
        if (++sc == STAGES) sc = 0;

        consume_kk(stA, stB, 0);
        consume_kk(stA, stB, 1);
    }

    if (KTAIL) {
        asm volatile("cp.async.wait_group 0;" ::: "memory");
        __syncthreads();
        const uint32_t stA = sb + sc * STAGE_BYTES;
        const uint32_t stB = stA + A_BYTES;
        consume_kk(stA, stB, 0);
    }

    // ---- epilogue ----
    const int lr = lane >> 2;
    const int lc = (lane & 3) * 2;
#pragma unroll
    for (int mi = 0; mi < 4; mi++) {
#pragma unroll
        for (int n8 = 0; n8 < NG; n8++) {
            int col = n0 + n8 * 8 + lc;
            float b0 = (col     < N) ? bias[col]     : 0.0f;
            float b1 = (col + 1 < N) ? bias[col + 1] : 0.0f;
#pragma unroll
            for (int h = 0; h < 2; h++) {
                int row = m0 + wid * 64 + mi * 16 + h * 8 + lr;
                float v0 = acc[mi][n8][2 * h + 0] + b0;
                float v1 = acc[mi][n8][2 * h + 1] + b1;
                __half2 hv;
                if (OUT == 1) {
                    v0 = (col     < N) ? fmaxf(v0, 0.0f) : 0.0f;
                    v1 = (col + 1 < N) ? fmaxf(v1, 0.0f) : 0.0f;
                    hv.x = __float2half(v0); hv.y = __float2half(v1);
                    *reinterpret_cast<__half2*>(&Ch[(size_t)row * ldc + col]) = hv;
                } else {
                    hv.x = __float2half(v0); hv.y = __float2half(v1);
                    size_t idx = ((size_t)(col >> 3) * B_ROWS + row) * 8 + (col & 7);
                    *reinterpret_cast<__half2*>(&Ch[idx]) = hv;
                }
            }
        }
    }
}

template <int OUT, int NG_LAST, bool KTAIL>
__global__ __launch_bounds__(128, 2) void gemm_mma(
    const __half* __restrict__ A, int lda, int Kiter,
    const __half* __restrict__ B, int ldb,
    const float* __restrict__ bias, int N,
    __half* __restrict__ Ch, int ldc, int m_base)
{
    extern __shared__ char smem[];
    const uint32_t sb = smem_u32(smem);
    const int n0 = blockIdx.x * 64;
    const int m0 = m_base + blockIdx.y * 256;
    if (NG_LAST != 0 && blockIdx.x == gridDim.x - 1) {
        gemm_body<OUT, NG_LAST, KTAIL>(A, lda, Kiter, B, ldb, bias, N, Ch, ldc, n0, m0, sb);
    } else {
        gemm_body<OUT, 8, KTAIL>(A, lda, Kiter, B, ldb, bias, N, Ch, ldc, n0, m0, sb);
    }
}

// ---------------- flow: one THREAD per batch row -------------------------------
__device__ __forceinline__ float h3grp(const uint4* G, int off) {
    const __half* h = reinterpret_cast<const __half*>(G);
    return __half2float(h[off]);
}

__global__ __launch_bounds__(256) void flow_kernel(
    const float* __restrict__ eps, float* __restrict__ out, int blk_base)
{
    __shared__ float sbuf[256 * A_DIM];
    const int tid = threadIdx.x;
    const int bid = blk_base + blockIdx.x;
    const size_t row = (size_t)bid * 256 + tid;

    {
        const float* src = eps + (size_t)bid * 256 * A_DIM;
#pragma unroll 4
        for (int i = tid; i < 256 * A_DIM; i += 256) sbuf[i] = src[i];
    }
    __syncthreads();

    float e[A_DIM];
#pragma unroll
    for (int a = 0; a < A_DIM; a++) e[a] = sbuf[tid * A_DIM + a];

    auto ldg8 = [&](int g) -> uint4 {
        return *reinterpret_cast<const uint4*>(g_h3 + ((size_t)g * B_ROWS + row) * 8);
    };

    float z[A_DIM];
    float lp = 0.0f;
    {
        uint4 G[5];
#pragma unroll
        for (int g = 0; g < 5; g++) G[g] = ldg8(g);
#pragma unroll
        for (int a = 0; a < A_DIM; a++) {
            float mu = ftanh(h3grp(G, a));
            float lv = ftanh(h3grp(G, 17 + a));
            z[a] = mu + fexp(lv) * e[a];
            lp += -0.5f * e[a] * e[a] - lv;
        }
    }

    uint4 GB[2];
    GB[0] = ldg8(68);
    GB[1] = ldg8(69);

    float ldj = 0.0f;
#pragma unroll
    for (int k = 0; k < K_FLOWS; k++) {
        const int bu = 34 + 17 * k;
        const int bw = 289 + 17 * k;
        const int gu0 = bu >> 3, ou = bu & 7;
        const int gw0 = bw >> 3, ow = bw & 7;
        uint4 GU[3], GW[3];
#pragma unroll
        for (int g = 0; g < 3; g++) { GU[g] = ldg8(gu0 + g); GW[g] = ldg8(gw0 + g); }

        float uw = 0.0f, wns = 0.0f, wz = 0.0f;
#pragma unroll
        for (int a = 0; a < A_DIM; a++) {
            float u = h3grp(GU, ou + a);
            float w = h3grp(GW, ow + a);
            uw  = fmaf(w, u, uw);
            wns = fmaf(w, w, wns);
            wz  = fmaf(w, z[a], wz);
        }
        float bk = h3grp(GB, k);

        float sp    = fmaxf(uw, 0.0f) + flog(1.0f + fexp(-fabsf(uw)));
        float m_uw  = -1.0f + sp;
        float scale = (m_uw - uw) / wns;
        float t     = ftanh(wz + bk);
#pragma unroll
        for (int a = 0; a < A_DIM; a++) {
            float u = h3grp(GU, ou + a);
            float w = h3grp(GW, ow + a);
            z[a] = fmaf(fmaf(scale, w, u), t, z[a]);
        }
        float psi_u = m_uw * (1.0f - t * t);
        ldj += flog(fabsf(1.0f + psi_u));
    }

    __syncthreads();
#pragma unroll
    for (int a = 0; a < A_DIM; a++) sbuf[tid * A_DIM + a] = z[a];
    __syncthreads();
    {
        float* dst = out + (size_t)bid * 256 * A_DIM;
#pragma unroll 4
        for (int i = tid; i < 256 * A_DIM; i += 256) dst[i] = sbuf[i];
    }

    lp -= 0.5f * (float)A_DIM * 1.8378770664093453f;
    float lpf = lp - ldj;
    out[(size_t)B_ROWS * A_DIM + row]          = fexp(lpf);
    out[(size_t)B_ROWS * A_DIM + B_ROWS + row] = lpf;
}

// ---------------- launch: two half-batch chains on forked streams --------------
extern "C" void kernel_launch(void* const* d_in, const int* in_sizes, int n_in,
                              void* d_out, int out_size)
{
    (void)in_sizes; (void)n_in; (void)out_size;

    const float* x   = (const float*)d_in[0];
    const float* eps = (const float*)d_in[1];
    const float* W1  = (const float*)d_in[2];
    const float* b1  = (const float*)d_in[3];
    const float* W2  = (const float*)d_in[4];
    const float* b2  = (const float*)d_in[5];
    const float* Wmu = (const float*)d_in[6];
    const float* bmu = (const float*)d_in[7];
    const float* Wlv = (const float*)d_in[8];
    const float* blv = (const float*)d_in[9];
    const float* Wu  = (const float*)d_in[10];
    const float* bu  = (const float*)d_in[11];
    const float* Ww  = (const float*)d_in[12];
    const float* bw  = (const float*)d_in[13];
    const float* Wb  = (const float*)d_in[14];
    const float* bb  = (const float*)d_in[15];
    float* out = (float*)d_out;

    __half *x16, *h1, *h2, *h3, *w1, *w2, *wh;
    float *bhp;
    cudaGetSymbolAddress((void**)&x16, g_x16);
    cudaGetSymbolAddress((void**)&h1,  g_h1);
    cudaGetSymbolAddress((void**)&h2,  g_h2);
    cudaGetSymbolAddress((void**)&h3,  g_h3);
    cudaGetSymbolAddress((void**)&w1,  g_W1);
    cudaGetSymbolAddress((void**)&w2,  g_W2);
    cudaGetSymbolAddress((void**)&wh,  g_Wh);
    cudaGetSymbolAddress((void**)&bhp, g_bh);

    // one-time stream/event setup (first call is the uncaptured correctness run)
    static bool init_done = false;
    static cudaStream_t s1, s2;
    static cudaEvent_t ev_root, ev_prep, ev_a, ev_b;
    if (!init_done) {
        cudaStreamCreateWithFlags(&s1, cudaStreamNonBlocking);
        cudaStreamCreateWithFlags(&s2, cudaStreamNonBlocking);
        cudaEventCreateWithFlags(&ev_root, cudaEventDisableTiming);
        cudaEventCreateWithFlags(&ev_prep, cudaEventDisableTiming);
        cudaEventCreateWithFlags(&ev_a,    cudaEventDisableTiming);
        cudaEventCreateWithFlags(&ev_b,    cudaEventDisableTiming);
        init_done = true;
    }

    const int smem_bytes = STAGES * STAGE_BYTES;   // 102400
    cudaFuncSetAttribute((const void*)gemm_mma<1, 2, false>, cudaFuncAttributeMaxDynamicSharedMemorySize, smem_bytes);
    cudaFuncSetAttribute((const void*)gemm_mma<1, 6, true>,  cudaFuncAttributeMaxDynamicSharedMemorySize, smem_bytes);
    cudaFuncSetAttribute((const void*)gemm_mma<0, 6, true>,  cudaFuncAttributeMaxDynamicSharedMemorySize, smem_bytes);

    const int HALF = B_ROWS / 2;            // 32768 rows per chain
    const int GY   = HALF / 256;            // 128 m-tiles per chain
    const int cvt_blocks = (HALF * (KP0 / 8) + 255) / 256;
    const int prep_total = W1_ELEMS + W2_ELEMS + WH_ELEMS;
    dim3 blk(128);

    // fork
    cudaEventRecord(ev_root, 0);
    cudaStreamWaitEvent(s1, ev_root, 0);
    cudaStreamWaitEvent(s2, ev_root, 0);

    // weights prep on s2 (both chains need it)
    prep_weights<<<(prep_total + 255) / 256, 256, 0, s2>>>(
        W1, W2, Wmu, bmu, Wlv, blv, Wu, bu, Ww, bw, Wb, bb);
    cudaEventRecord(ev_prep, s2);

    // ---- chain A (rows 0 .. 32767) on s1 ----
    convert_x<<<cvt_blocks, 256, 0, s1>>>(x, x16, 0);
    cudaStreamWaitEvent(s1, ev_prep, 0);
    gemm_mma<1, 2, false><<<dim3(7, GY), blk, smem_bytes, s1>>>(
        x16, KP0, KP0, w1, NB1, b1, H1_DIM, h1, NB1, 0);
    gemm_mma<1, 6, true><<<dim3(5, GY), blk, smem_bytes, s1>>>(
        h1, NB1, KI1, w2, NB2, b2, H2_DIM, h2, NB2, 0);
    gemm_mma<0, 6, true><<<dim3(9, GY), blk, smem_bytes, s1>>>(
        h2, KP2, KP2, wh, NB3, bhp, HEAD_N, h3, NB3, 0);
    flow_kernel<<<HALF / 256, 256, 0, s1>>>(eps, out, 0);
    cudaEventRecord(ev_a, s1);

    // ---- chain B (rows 32768 .. 65535) on s2 ----
    convert_x<<<cvt_blocks, 256, 0, s2>>>(x, x16, HALF);
    gemm_mma<1, 2, false><<<dim3(7, GY), blk, smem_bytes, s2>>>(
        x16, KP0, KP0, w1, NB1, b1, H1_DIM, h1, NB1, HALF);
    gemm_mma<1, 6, true><<<dim3(5, GY), blk, smem_bytes, s2>>>(
        h1, NB1, KI1, w2, NB2, b2, H2_DIM, h2, NB2, HALF);
    gemm_mma<0, 6, true><<<dim3(9, GY), blk, smem_bytes, s2>>>(
        h2, KP2, KP2, wh, NB3, bhp, HEAD_N, h3, NB3, HALF);
    flow_kernel<<<HALF / 256, 256, 0, s2>>>(eps, out, HALF / 256);
    cudaEventRecord(ev_b, s2);

    // join back to the launch stream
    cudaStreamWaitEvent(0, ev_a, 0);
    cudaStreamWaitEvent(0, ev_b, 0);
}